// round 7
// baseline (speedup 1.0000x reference)
#include <cuda_runtime.h>
#include <cstdint>
#include <cstddef>

#define BB 32
#define NN 512
#define CC 768
#define HH 12
#define HD 64
#define MTOT (BB*NN)      // 16384
#define NC3 (3*CC)        // 2304

typedef signed char s8;

// ---------------- device scratch (allocation-free) ----------------
__device__ float g_sc[8]; // 0:a_in 1:qa 2:ka 3:va 4:aa 5:pa 6:cs1 7:apx
__device__ s8    g_xq[MTOT*CC];
__device__ s8    g_wq[NC3*CC];
__device__ float g_bi[NC3];
__device__ s8    g_q2[BB*HH*NN*HD];
__device__ s8    g_k2[BB*HH*NN*HD];
__device__ s8    g_v2t[BB*HH*HD*NN];   // [bh][d][n]
__device__ s8    g_x1[MTOT*CC];
__device__ s8    g_pw[CC*CC];

__device__ __forceinline__ float warp_sum(float v){
#pragma unroll
    for (int o = 16; o > 0; o >>= 1)
        v = __fadd_rn(v, __shfl_xor_sync(0xffffffffu, v, o));
    return v;
}

__device__ __forceinline__ s8 q_rc(float v, float a, float lo, float hi){
    float r = __fdiv_rn(v, a);
    r = fminf(fmaxf(r, lo), hi);
    return (s8)(int)rintf(r);
}

// exact 2^ei for integer ei >= -126
__device__ __forceinline__ float p2i(int ei){
    int ec = max(ei, -126);
    return __int_as_float((ec + 127) << 23);
}

__device__ __forceinline__ void mma_s8(int* d, const int* a, const int* b){
    asm volatile(
        "mma.sync.aligned.m16n8k32.row.col.s32.s8.s8.s32 "
        "{%0,%1,%2,%3}, {%4,%5,%6,%7}, {%8,%9}, {%0,%1,%2,%3};"
        : "+r"(d[0]), "+r"(d[1]), "+r"(d[2]), "+r"(d[3])
        : "r"(a[0]), "r"(a[1]), "r"(a[2]), "r"(a[3]), "r"(b[0]), "r"(b[1]));
}

__device__ __forceinline__ uint32_t smem_u32(const void* p){
    uint32_t a;
    asm("{ .reg .u64 t; cvta.to.shared.u64 t, %1; cvt.u32.u64 %0, t; }" : "=r"(a) : "l"(p));
    return a;
}
__device__ __forceinline__ void cpa16(uint32_t dst, const void* src){
    asm volatile("cp.async.ca.shared.global [%0], [%1], 16;" :: "r"(dst), "l"(src));
}
#define CPA_COMMIT() asm volatile("cp.async.commit_group;" ::: "memory")
#define CPA_WAIT(n)  asm volatile("cp.async.wait_group %0;" :: "n"(n) : "memory")

// ---------------- scalar means + integer bias ----------------
__global__ void k_scalars(const float* __restrict__ qaa, const float* __restrict__ qact,
                          const float* __restrict__ kact, const float* __restrict__ vact,
                          const float* __restrict__ aact, const float* __restrict__ paa,
                          const float* __restrict__ qkv_bias, const float* __restrict__ qkv_alpha){
    int tid = threadIdx.x;
    if (tid < 32){
        int lane = tid;
        float s = 0.f;
        for (int i = lane; i < 768; i += 32) s = __fadd_rn(s, qaa[i]);
        float a_in = __fdiv_rn(warp_sum(s), 768.0f);
        s = 0.f;
        for (int i = lane; i < 768; i += 32) s = __fadd_rn(s, paa[i]);
        float pa = __fdiv_rn(warp_sum(s), 768.0f);
        float t;
        t = (lane < 12) ? qact[lane] : 0.f; float qa = __fdiv_rn(warp_sum(t), 12.0f);
        t = (lane < 12) ? kact[lane] : 0.f; float ka = __fdiv_rn(warp_sum(t), 12.0f);
        t = (lane < 12) ? vact[lane] : 0.f; float va = __fdiv_rn(warp_sum(t), 12.0f);
        t = (lane < 12) ? aact[lane] : 0.f; float aa = __fdiv_rn(warp_sum(t), 12.0f);
        if (lane == 0){
            g_sc[0] = a_in; g_sc[1] = qa; g_sc[2] = ka; g_sc[3] = va; g_sc[4] = aa; g_sc[5] = pa;
            float sm = __fmul_rn(__fmul_rn(0.125f, qa), ka);
            g_sc[6] = __fmul_rn(1.4426950408889634f, sm);
            g_sc[7] = __fdiv_rn(pa, __fmul_rn(aa, va));
        }
    }
    __syncthreads();
    float a_in = g_sc[0];
    for (int j = tid; j < NC3; j += 256)
        g_bi[j] = truncf(__fdiv_rn(__fdiv_rn(qkv_bias[j], a_in), qkv_alpha[j]));
}

// ---------------- input/weight quantization ----------------
__global__ void k_quant_x(const float* __restrict__ x){
    float a = g_sc[0];
    int base = blockIdx.x * 1024 + threadIdx.x;
#pragma unroll
    for (int p = 0; p < 4; p++){
        int idx = base + p * 256;
        float4 v = ((const float4*)x)[idx];
        char4 c;
        c.x = q_rc(v.x, a, -8.f, 7.f); c.y = q_rc(v.y, a, -8.f, 7.f);
        c.z = q_rc(v.z, a, -8.f, 7.f); c.w = q_rc(v.w, a, -8.f, 7.f);
        ((char4*)g_xq)[idx] = c;
    }
}

__global__ void k_quant_w(const float* __restrict__ w, const float* __restrict__ al){
    int idx = blockIdx.x * 256 + threadIdx.x;
    int row = idx / 192;
    float a = al[row];
    float4 v = ((const float4*)w)[idx];
    char4 c;
    c.x = q_rc(v.x, a, -8.f, 7.f); c.y = q_rc(v.y, a, -8.f, 7.f);
    c.z = q_rc(v.z, a, -8.f, 7.f); c.w = q_rc(v.w, a, -8.f, 7.f);
    ((char4*)g_wq)[idx] = c;
}

__global__ void k_quant_pw(const float* __restrict__ w, const float* __restrict__ al){
    int idx = blockIdx.x * 256 + threadIdx.x;
    int row = idx / 192;
    float a = al[row];
    float4 v = ((const float4*)w)[idx];
    char4 c;
    c.x = q_rc(v.x, a, -8.f, 7.f); c.y = q_rc(v.y, a, -8.f, 7.f);
    c.z = q_rc(v.z, a, -8.f, 7.f); c.w = q_rc(v.w, a, -8.f, 7.f);
    ((char4*)g_pw)[idx] = c;
}

// ---------------- GEMM compute tile (shared by gemm1/gemm2) ----------------
__device__ __forceinline__ void gemm_stage_compute(
        const s8* Atile, const s8* Btile, int lane, int wrBase, int wcBase,
        int acc[4][4][4]){
#pragma unroll
    for (int s = 0; s < 4; s++){
        int c4 = (lane & 3) * 4;
        int afr[4][4];
#pragma unroll
        for (int mt = 0; mt < 4; mt++){
            int r0 = wrBase + mt * 16 + (lane >> 2);
            int r1 = r0 + 8;
            afr[mt][0] = *(const int*)(Atile + r0*128 + (((2*s  ) ^ (r0 & 7)) * 16) + c4);
            afr[mt][1] = *(const int*)(Atile + r1*128 + (((2*s  ) ^ (r1 & 7)) * 16) + c4);
            afr[mt][2] = *(const int*)(Atile + r0*128 + (((2*s+1) ^ (r0 & 7)) * 16) + c4);
            afr[mt][3] = *(const int*)(Atile + r1*128 + (((2*s+1) ^ (r1 & 7)) * 16) + c4);
        }
        int bfr[4][2];
#pragma unroll
        for (int nt = 0; nt < 4; nt++){
            int c0 = wcBase + nt * 8 + (lane >> 2);
            bfr[nt][0] = *(const int*)(Btile + c0*128 + (((2*s  ) ^ (c0 & 7)) * 16) + c4);
            bfr[nt][1] = *(const int*)(Btile + c0*128 + (((2*s+1) ^ (c0 & 7)) * 16) + c4);
        }
#pragma unroll
        for (int mt = 0; mt < 4; mt++)
#pragma unroll
            for (int nt = 0; nt < 4; nt++)
                mma_s8(acc[mt][nt], afr[mt], bfr[nt]);
    }
}

__device__ __forceinline__ void gemm_stage_load(
        uint32_t smb, int stage, int tid,
        const s8* __restrict__ Ag, const s8* __restrict__ Bg, int kt){
    uint32_t sA = smb + stage * 32768;
    uint32_t sB = sA + 16384;
#pragma unroll
    for (int p = 0; p < 4; p++){
        int idx = tid + p * 256;
        int r = idx >> 3, seg = idx & 7;
        uint32_t off = r * 128 + ((seg ^ (r & 7)) * 16);
        cpa16(sA + off, Ag + (size_t)r * 768 + kt + seg * 16);
        cpa16(sB + off, Bg + (size_t)r * 768 + kt + seg * 16);
    }
}

// ---------------- QKV GEMM (mma.sync + cp.async pipeline) + LN/quant epilogue ----------------
// grid (18, 128), 256 threads, dyn smem 67584
__global__ void __launch_bounds__(256) k_gemm1(
        const float* __restrict__ qkv_alpha,
        const float* __restrict__ nqw, const float* __restrict__ nqb,
        const float* __restrict__ nkw, const float* __restrict__ nkb){
    extern __shared__ int smw[];
    uint32_t smb = smem_u32(smw);
    int tid = threadIdx.x, lane = tid & 31, wid = tid >> 5;
    int wrBase = (wid >> 2) * 64;
    int wcBase = (wid & 3) * 32;
    int rowBase = blockIdx.y << 7, colBase = blockIdx.x << 7;
    const s8* Ag = g_xq + (size_t)rowBase * 768;
    const s8* Bg = g_wq + (size_t)colBase * 768;

    int acc[4][4][4];
#pragma unroll
    for (int mt = 0; mt < 4; mt++)
#pragma unroll
        for (int nt = 0; nt < 4; nt++)
#pragma unroll
            for (int q = 0; q < 4; q++) acc[mt][nt][q] = 0;

    gemm_stage_load(smb, 0, tid, Ag, Bg, 0);
    CPA_COMMIT();
    for (int kc = 0; kc < 6; kc++){
        if (kc < 5){
            gemm_stage_load(smb, (kc + 1) & 1, tid, Ag, Bg, (kc + 1) * 128);
            CPA_COMMIT();
            CPA_WAIT(1);
        } else {
            CPA_WAIT(0);
        }
        __syncthreads();
        const s8* Atile = (const s8*)smw + (kc & 1) * 32768;
        const s8* Btile = Atile + 16384;
        gemm_stage_compute(Atile, Btile, lane, wrBase, wcBase, acc);
        __syncthreads();
    }

    // stage C tile in smem: [128][132]
    int* Cs = smw;
#pragma unroll
    for (int mt = 0; mt < 4; mt++)
#pragma unroll
        for (int nt = 0; nt < 4; nt++){
            int r0 = wrBase + mt * 16 + (lane >> 2);
            int cl = wcBase + nt * 8 + 2 * (lane & 3);
            Cs[r0 * 132 + cl]           = acc[mt][nt][0];
            Cs[r0 * 132 + cl + 1]       = acc[mt][nt][1];
            Cs[(r0 + 8) * 132 + cl]     = acc[mt][nt][2];
            Cs[(r0 + 8) * 132 + cl + 1] = acc[mt][nt][3];
        }
    __syncthreads();

    float a_in = g_sc[0];
    for (int it = wid; it < 256; it += 8){
        int r = it >> 1, g = it & 1;
        int th = (blockIdx.x << 1) + g;
        int t  = th / 12, h = th - 12 * t;
        int row = rowBase + r;
        int b_ = row >> 9, n = row & 511;
        int d0 = lane * 2;
        int jg = th * 64;
        float al0 = qkv_alpha[jg + d0], al1 = qkv_alpha[jg + d0 + 1];
        float c0 = __fadd_rn((float)Cs[r*132 + g*64 + d0],     g_bi[jg + d0]);
        float c1 = __fadd_rn((float)Cs[r*132 + g*64 + d0 + 1], g_bi[jg + d0 + 1]);
        if (t == 2){
            float va = g_sc[3];
            float ap0 = __fdiv_rn(va, __fmul_rn(a_in, al0));
            float ap1 = __fdiv_rn(va, __fmul_rn(a_in, al1));
            float r0 = fminf(fmaxf(__fdiv_rn(c0, ap0), -4.f), 3.f);
            float r1 = fminf(fmaxf(__fdiv_rn(c1, ap1), -4.f), 3.f);
            s8* dst = g_v2t + (size_t)(b_*12 + h) * 64 * 512;
            dst[(size_t)d0 * 512 + n]       = (s8)(int)rintf(r0);
            dst[(size_t)(d0+1) * 512 + n]   = (s8)(int)rintf(r1);
        } else {
            float xs0 = __fmul_rn(c0, al0), xs1 = __fmul_rn(c1, al1);
            float ssum = warp_sum(__fadd_rn(xs0, xs1));
            float mean = __fdiv_rn(ssum, 64.0f);
            float dv0 = __fadd_rn(xs0, -mean), dv1 = __fadd_rn(xs1, -mean);
            float vs = warp_sum(__fadd_rn(__fmul_rn(dv0, dv0), __fmul_rn(dv1, dv1)));
            float stdv = __fsqrt_rn(__fdiv_rn(vs, 63.0f));
            float den = __fadd_rn(stdv, 1e-5f);
            float xh0 = __fdiv_rn(dv0, den), xh1 = __fdiv_rn(dv1, den);
            const float* w  = (t == 0) ? nqw : nkw;
            const float* bb = (t == 0) ? nqb : nkb;
            float act = (t == 0) ? g_sc[1] : g_sc[2];
            float w0 = w[d0], w1 = w[d0 + 1];
            float alp0 = __fdiv_rn(act, w0), alp1 = __fdiv_rn(act, w1);
            float bi0 = __fdiv_rn(bb[d0], w0), bi1 = __fdiv_rn(bb[d0 + 1], w1);
            float r0 = fminf(fmaxf(__fdiv_rn(__fadd_rn(xh0, bi0), alp0), -4.f), 3.f);
            float r1 = fminf(fmaxf(__fdiv_rn(__fadd_rn(xh1, bi1), alp1), -4.f), 3.f);
            s8* dst = (t == 0) ? g_q2 : g_k2;
            size_t o = ((size_t)(b_*12 + h) * 512 + n) * 64 + d0;
            dst[o]     = (s8)(int)rintf(r0);
            dst[o + 1] = (s8)(int)rintf(r1);
        }
    }
}

// ---------------- attention: QK^T, softmax2, quant(LUT), AV ----------------
// grid (384, 8), 256 threads, dyn smem 72960; K/V share one buffer (phased)
// NOTE: no min-blocks clause — reg cap caused spills (R4, R6 regressions)
#define DP16(sacc, ar, b0, b1, b2, b3)                   \
    sacc = __dp4a((ar)[0],  (b0).x, sacc); sacc = __dp4a((ar)[1],  (b0).y, sacc); \
    sacc = __dp4a((ar)[2],  (b0).z, sacc); sacc = __dp4a((ar)[3],  (b0).w, sacc); \
    sacc = __dp4a((ar)[4],  (b1).x, sacc); sacc = __dp4a((ar)[5],  (b1).y, sacc); \
    sacc = __dp4a((ar)[6],  (b1).z, sacc); sacc = __dp4a((ar)[7],  (b1).w, sacc); \
    sacc = __dp4a((ar)[8],  (b2).x, sacc); sacc = __dp4a((ar)[9],  (b2).y, sacc); \
    sacc = __dp4a((ar)[10], (b2).z, sacc); sacc = __dp4a((ar)[11], (b2).w, sacc); \
    sacc = __dp4a((ar)[12], (b3).x, sacc); sacc = __dp4a((ar)[13], (b3).y, sacc); \
    sacc = __dp4a((ar)[14], (b3).z, sacc); sacc = __dp4a((ar)[15], (b3).w, sacc)

__global__ void __launch_bounds__(256) k_attn(){
    extern __shared__ int smw[];
    int*   kv   = smw;                        // 8448 ints: K phase rows ki*16; V phase d*132
    int*   es   = smw + 8448;                 // 8448 ints
    float* rs2  = (float*)(smw + 16896);      // 256
    float* rsum = rs2 + 256;                  // 64
    s8*    lut  = (s8*)(rsum + 64);           // 64 x 64

    int tid = threadIdx.x;
    int bh = blockIdx.x, qt = blockIdx.y;
    size_t base = (size_t)bh * 512 * 64;

    const int4* kg = (const int4*)(g_k2 + base);
#pragma unroll
    for (int i = tid; i < 2048; i += 256) ((int4*)kv)[i] = kg[i];

    int qi = tid >> 2, qr = tid & 3;
    // Q row direct from gmem (4-thread broadcast per row)
    const int4* qg = (const int4*)(g_q2 + base + (size_t)qt * 4096 + (size_t)qi * 64);
    int areg[16];
    {
        int4 a0 = qg[0], a1 = qg[1], a2 = qg[2], a3 = qg[3];
        areg[0]=a0.x; areg[1]=a0.y; areg[2]=a0.z; areg[3]=a0.w;
        areg[4]=a1.x; areg[5]=a1.y; areg[6]=a1.z; areg[7]=a1.w;
        areg[8]=a2.x; areg[9]=a2.y; areg[10]=a2.z; areg[11]=a2.w;
        areg[12]=a3.x; areg[13]=a3.y; areg[14]=a3.z; areg[15]=a3.w;
    }
    __syncthreads();

    float cs1 = g_sc[6];
    float psum = 0.f;
    int packed = 0;
    for (int i = 0; i < 128; i++){
        int ki = qr * 128 + i;
        const int4* kr = (const int4*)&kv[ki * 16];
        int4 b0 = kr[0], b1 = kr[1], b2 = kr[2], b3 = kr[3];
        int s = 0;
        DP16(s, areg, b0, b1, b2, b3);
        float e = truncf(__fmul_rn(__fmul_rn(cs1, (float)s), 128.0f));
        int ei = (int)rintf(__fmul_rn(e, 0.0078125f));
        psum = __fadd_rn(psum, p2i(ei));
        packed |= (ei & 0xff) << ((i & 3) * 8);
        if ((i & 3) == 3){ es[qi * 132 + (ki >> 2)] = packed; packed = 0; }
    }
    rs2[qi * 4 + qr] = psum;
    __syncthreads();   // all QK reads of kv complete

    // phase 2: load V into kv (reuse) + reduce row sums
    const int4* vg = (const int4*)(g_v2t + base);
#pragma unroll
    for (int i = tid; i < 2048; i += 256){
        int d = i >> 5, seg = i & 31;
        ((int4*)&kv[d * 132])[seg] = vg[i];
    }
    if (tid < 64){
        float s = __fadd_rn(__fadd_rn(__fadd_rn(rs2[tid*4], rs2[tid*4+1]), rs2[tid*4+2]), rs2[tid*4+3]);
        rsum[tid] = s;
    }
    __syncthreads();

    // per-row quantization LUT (identical op sequence to direct path)
    float aa = g_sc[4];
    for (int w = tid; w < 4096; w += 256){
        int row = w >> 6, j = w & 63;
        float p = p2i(j - 32);
        float su = rsum[row];
        float r = fminf(fmaxf(__fdiv_rn(__fdiv_rn(p, su), aa), 0.f), 7.f);
        lut[w] = (s8)(int)rintf(r);
    }
    __syncthreads();

    // quantize attention in place via LUT
    for (int w = tid; w < 8192; w += 256){
        int q2i = w >> 7, k4 = w & 127;
        int e4 = es[q2i * 132 + k4];
        const s8* lr = lut + (q2i << 6);
        int out = 0;
#pragma unroll
        for (int b = 0; b < 4; b++){
            int ei = (int)(s8)(e4 >> (b * 8));
            int j = min(max(ei + 32, 0), 63);
            out |= ((int)lr[j]) << (b * 8);
        }
        es[q2i * 132 + k4] = out;
    }
    __syncthreads();

    // AV
    int acc[16];
#pragma unroll
    for (int dd = 0; dd < 16; dd++) acc[dd] = 0;
#pragma unroll
    for (int c = 0; c < 8; c++){
        int aw[16];
#pragma unroll
        for (int w = 0; w < 16; w++) aw[w] = es[qi * 132 + c * 16 + w];
#pragma unroll
        for (int dd = 0; dd < 16; dd++){
            int d = qr + 4 * dd;
            const int4* vr = (const int4*)&kv[d * 132 + c * 16];
            int4 v0 = vr[0], v1 = vr[1], v2 = vr[2], v3 = vr[3];
            int s = acc[dd];
            DP16(s, aw, v0, v1, v2, v3);
            acc[dd] = s;
        }
    }
    float apx = g_sc[7];
    int b_ = bh / 12, h = bh - 12 * b_;
    int row = b_ * 512 + qt * 64 + qi;
    s8* dst = g_x1 + (size_t)row * 768 + h * 64;
#pragma unroll
    for (int dd = 0; dd < 16; dd++){
        float r = fminf(fmaxf(__fdiv_rn((float)acc[dd], apx), -4.f), 3.f);
        dst[qr + 4 * dd] = (s8)(int)rintf(r);
    }
}

// ---------------- projection GEMM (mma.sync + cp.async pipeline) ----------------
// grid (6, 128), 256 threads, dyn smem 65536
__global__ void __launch_bounds__(256) k_gemm2(
        const float* __restrict__ palpha, const float* __restrict__ pbias,
        float* __restrict__ out){
    extern __shared__ int smw[];
    uint32_t smb = smem_u32(smw);
    int tid = threadIdx.x, lane = tid & 31, wid = tid >> 5;
    int wrBase = (wid >> 2) * 64;
    int wcBase = (wid & 3) * 32;
    int rowBase = blockIdx.y << 7, colBase = blockIdx.x << 7;
    const s8* Ag = g_x1 + (size_t)rowBase * 768;
    const s8* Bg = g_pw + (size_t)colBase * 768;

    int acc[4][4][4];
#pragma unroll
    for (int mt = 0; mt < 4; mt++)
#pragma unroll
        for (int nt = 0; nt < 4; nt++)
#pragma unroll
            for (int q = 0; q < 4; q++) acc[mt][nt][q] = 0;

    gemm_stage_load(smb, 0, tid, Ag, Bg, 0);
    CPA_COMMIT();
    for (int kc = 0; kc < 6; kc++){
        if (kc < 5){
            gemm_stage_load(smb, (kc + 1) & 1, tid, Ag, Bg, (kc + 1) * 128);
            CPA_COMMIT();
            CPA_WAIT(1);
        } else {
            CPA_WAIT(0);
        }
        __syncthreads();
        const s8* Atile = (const s8*)smw + (kc & 1) * 32768;
        const s8* Btile = Atile + 16384;
        gemm_stage_compute(Atile, Btile, lane, wrBase, wcBase, acc);
        __syncthreads();
    }

    float pa = g_sc[5];
#pragma unroll
    for (int mt = 0; mt < 4; mt++)
#pragma unroll
        for (int nt = 0; nt < 4; nt++){
            int r0 = rowBase + wrBase + mt * 16 + (lane >> 2);
            int c  = colBase + wcBase + nt * 8 + 2 * (lane & 3);
            float al0 = palpha[c], al1 = palpha[c + 1];
            float bi0 = pbias[c],  bi1 = pbias[c + 1];
            out[(size_t)r0 * 768 + c]
                = __fadd_rn(__fmul_rn(__fmul_rn((float)acc[mt][nt][0], al0), pa), bi0);
            out[(size_t)r0 * 768 + c + 1]
                = __fadd_rn(__fmul_rn(__fmul_rn((float)acc[mt][nt][1], al1), pa), bi1);
            out[(size_t)(r0 + 8) * 768 + c]
                = __fadd_rn(__fmul_rn(__fmul_rn((float)acc[mt][nt][2], al0), pa), bi0);
            out[(size_t)(r0 + 8) * 768 + c + 1]
                = __fadd_rn(__fmul_rn(__fmul_rn((float)acc[mt][nt][3], al1), pa), bi1);
        }
}

// ---------------- launch ----------------
extern "C" void kernel_launch(void* const* d_in, const int* in_sizes, int n_in,
                              void* d_out, int out_size){
    const float* x0          = (const float*)d_in[0];
    const float* qkv_w       = (const float*)d_in[1];
    const float* qkv_alpha   = (const float*)d_in[2];
    const float* qkv_bias    = (const float*)d_in[3];
    const float* qkv_act_al  = (const float*)d_in[4];
    const float* proj_w      = (const float*)d_in[5];
    const float* proj_alpha  = (const float*)d_in[6];
    const float* proj_bias   = (const float*)d_in[7];
    const float* proj_act_al = (const float*)d_in[8];
    const float* normq_w     = (const float*)d_in[9];
    const float* normq_b     = (const float*)d_in[10];
    const float* normk_w     = (const float*)d_in[11];
    const float* normk_b     = (const float*)d_in[12];
    const float* qact        = (const float*)d_in[13];
    const float* kact        = (const float*)d_in[14];
    const float* vact        = (const float*)d_in[15];
    const float* attnact     = (const float*)d_in[16];
    float* out = (float*)d_out;

    cudaFuncSetAttribute(k_gemm1, cudaFuncAttributeMaxDynamicSharedMemorySize, 67584);
    cudaFuncSetAttribute(k_gemm2, cudaFuncAttributeMaxDynamicSharedMemorySize, 65536);
    cudaFuncSetAttribute(k_attn,  cudaFuncAttributeMaxDynamicSharedMemorySize, 72960);

    k_scalars<<<1, 256>>>(qkv_act_al, qact, kact, vact, attnact, proj_act_al,
                          qkv_bias, qkv_alpha);
    k_quant_x<<<3072, 256>>>(x0);
    k_quant_w<<<1728, 256>>>(qkv_w, qkv_alpha);
    k_gemm1<<<dim3(18, 128), 256, 67584>>>(qkv_alpha, normq_w, normq_b, normk_w, normk_b);
    k_attn<<<dim3(384, 8), 256, 72960>>>();
    k_quant_pw<<<576, 256>>>(proj_w, proj_alpha);
    k_gemm2<<<dim3(6, 128), 256, 65536>>>(proj_alpha, proj_bias, out);
}

// round 8
// speedup vs baseline: 1.0577x; 1.0577x over previous
#include <cuda_runtime.h>
#include <cstdint>
#include <cstddef>

#define BB 32
#define NN 512
#define CC 768
#define HH 12
#define HD 64
#define MTOT (BB*NN)      // 16384
#define NC3 (3*CC)        // 2304

typedef signed char s8;

// ---------------- device scratch (allocation-free) ----------------
__device__ float g_sc[8]; // 0:a_in 1:qa 2:ka 3:va 4:aa 5:pa 6:cs1 7:apx
__device__ s8    g_xq[MTOT*CC];
__device__ s8    g_wq[NC3*CC];
__device__ float g_bi[NC3];
__device__ s8    g_q2[BB*HH*NN*HD];
__device__ s8    g_k2[BB*HH*NN*HD];
__device__ s8    g_v2t[BB*HH*HD*NN];   // [bh][d][n]
__device__ s8    g_x1[MTOT*CC];
__device__ s8    g_pw[CC*CC];

__device__ __forceinline__ float warp_sum(float v){
#pragma unroll
    for (int o = 16; o > 0; o >>= 1)
        v = __fadd_rn(v, __shfl_xor_sync(0xffffffffu, v, o));
    return v;
}

__device__ __forceinline__ s8 q_rc(float v, float a, float lo, float hi){
    float r = __fdiv_rn(v, a);
    r = fminf(fmaxf(r, lo), hi);
    return (s8)(int)rintf(r);
}

// exact 2^ei for integer ei >= -126
__device__ __forceinline__ float p2i(int ei){
    int ec = max(ei, -126);
    return __int_as_float((ec + 127) << 23);
}

__device__ __forceinline__ void mma_s8(int* d, const int* a, const int* b){
    asm volatile(
        "mma.sync.aligned.m16n8k32.row.col.s32.s8.s8.s32 "
        "{%0,%1,%2,%3}, {%4,%5,%6,%7}, {%8,%9}, {%0,%1,%2,%3};"
        : "+r"(d[0]), "+r"(d[1]), "+r"(d[2]), "+r"(d[3])
        : "r"(a[0]), "r"(a[1]), "r"(a[2]), "r"(a[3]), "r"(b[0]), "r"(b[1]));
}

__device__ __forceinline__ uint32_t smem_u32(const void* p){
    uint32_t a;
    asm("{ .reg .u64 t; cvta.to.shared.u64 t, %1; cvt.u32.u64 %0, t; }" : "=r"(a) : "l"(p));
    return a;
}
__device__ __forceinline__ void cpa16(uint32_t dst, const void* src){
    asm volatile("cp.async.ca.shared.global [%0], [%1], 16;" :: "r"(dst), "l"(src));
}
#define CPA_COMMIT() asm volatile("cp.async.commit_group;" ::: "memory")
#define CPA_WAIT(n)  asm volatile("cp.async.wait_group %0;" :: "n"(n) : "memory")

// ---------------- scalar means + integer bias ----------------
__global__ void k_scalars(const float* __restrict__ qaa, const float* __restrict__ qact,
                          const float* __restrict__ kact, const float* __restrict__ vact,
                          const float* __restrict__ aact, const float* __restrict__ paa,
                          const float* __restrict__ qkv_bias, const float* __restrict__ qkv_alpha){
    int tid = threadIdx.x;
    if (tid < 32){
        int lane = tid;
        float s = 0.f;
        for (int i = lane; i < 768; i += 32) s = __fadd_rn(s, qaa[i]);
        float a_in = __fdiv_rn(warp_sum(s), 768.0f);
        s = 0.f;
        for (int i = lane; i < 768; i += 32) s = __fadd_rn(s, paa[i]);
        float pa = __fdiv_rn(warp_sum(s), 768.0f);
        float t;
        t = (lane < 12) ? qact[lane] : 0.f; float qa = __fdiv_rn(warp_sum(t), 12.0f);
        t = (lane < 12) ? kact[lane] : 0.f; float ka = __fdiv_rn(warp_sum(t), 12.0f);
        t = (lane < 12) ? vact[lane] : 0.f; float va = __fdiv_rn(warp_sum(t), 12.0f);
        t = (lane < 12) ? aact[lane] : 0.f; float aa = __fdiv_rn(warp_sum(t), 12.0f);
        if (lane == 0){
            g_sc[0] = a_in; g_sc[1] = qa; g_sc[2] = ka; g_sc[3] = va; g_sc[4] = aa; g_sc[5] = pa;
            float sm = __fmul_rn(__fmul_rn(0.125f, qa), ka);
            g_sc[6] = __fmul_rn(1.4426950408889634f, sm);
            g_sc[7] = __fdiv_rn(pa, __fmul_rn(aa, va));
        }
    }
    __syncthreads();
    float a_in = g_sc[0];
    for (int j = tid; j < NC3; j += 256)
        g_bi[j] = truncf(__fdiv_rn(__fdiv_rn(qkv_bias[j], a_in), qkv_alpha[j]));
}

// ---------------- fused input+weight quantization (x: blocks 0..3071, w: 3072..4799) ----------------
__global__ void k_quant_xw(const float* __restrict__ x, const float* __restrict__ w,
                           const float* __restrict__ al){
    if (blockIdx.x < 3072){
        float a = g_sc[0];
        int base = blockIdx.x * 1024 + threadIdx.x;
#pragma unroll
        for (int p = 0; p < 4; p++){
            int idx = base + p * 256;
            float4 v = ((const float4*)x)[idx];
            char4 c;
            c.x = q_rc(v.x, a, -8.f, 7.f); c.y = q_rc(v.y, a, -8.f, 7.f);
            c.z = q_rc(v.z, a, -8.f, 7.f); c.w = q_rc(v.w, a, -8.f, 7.f);
            ((char4*)g_xq)[idx] = c;
        }
    } else {
        int idx = (blockIdx.x - 3072) * 256 + threadIdx.x;
        int row = idx / 192;
        float a = al[row];
        float4 v = ((const float4*)w)[idx];
        char4 c;
        c.x = q_rc(v.x, a, -8.f, 7.f); c.y = q_rc(v.y, a, -8.f, 7.f);
        c.z = q_rc(v.z, a, -8.f, 7.f); c.w = q_rc(v.w, a, -8.f, 7.f);
        ((char4*)g_wq)[idx] = c;
    }
}

__global__ void k_quant_pw(const float* __restrict__ w, const float* __restrict__ al){
    int idx = blockIdx.x * 256 + threadIdx.x;
    int row = idx / 192;
    float a = al[row];
    float4 v = ((const float4*)w)[idx];
    char4 c;
    c.x = q_rc(v.x, a, -8.f, 7.f); c.y = q_rc(v.y, a, -8.f, 7.f);
    c.z = q_rc(v.z, a, -8.f, 7.f); c.w = q_rc(v.w, a, -8.f, 7.f);
    ((char4*)g_pw)[idx] = c;
}

// ---------------- GEMM compute tile (shared by gemm1/gemm2) ----------------
__device__ __forceinline__ void gemm_stage_compute(
        const s8* Atile, const s8* Btile, int lane, int wrBase, int wcBase,
        int acc[4][4][4]){
#pragma unroll
    for (int s = 0; s < 4; s++){
        int c4 = (lane & 3) * 4;
        int afr[4][4];
#pragma unroll
        for (int mt = 0; mt < 4; mt++){
            int r0 = wrBase + mt * 16 + (lane >> 2);
            int r1 = r0 + 8;
            afr[mt][0] = *(const int*)(Atile + r0*128 + (((2*s  ) ^ (r0 & 7)) * 16) + c4);
            afr[mt][1] = *(const int*)(Atile + r1*128 + (((2*s  ) ^ (r1 & 7)) * 16) + c4);
            afr[mt][2] = *(const int*)(Atile + r0*128 + (((2*s+1) ^ (r0 & 7)) * 16) + c4);
            afr[mt][3] = *(const int*)(Atile + r1*128 + (((2*s+1) ^ (r1 & 7)) * 16) + c4);
        }
        int bfr[4][2];
#pragma unroll
        for (int nt = 0; nt < 4; nt++){
            int c0 = wcBase + nt * 8 + (lane >> 2);
            bfr[nt][0] = *(const int*)(Btile + c0*128 + (((2*s  ) ^ (c0 & 7)) * 16) + c4);
            bfr[nt][1] = *(const int*)(Btile + c0*128 + (((2*s+1) ^ (c0 & 7)) * 16) + c4);
        }
#pragma unroll
        for (int mt = 0; mt < 4; mt++)
#pragma unroll
            for (int nt = 0; nt < 4; nt++)
                mma_s8(acc[mt][nt], afr[mt], bfr[nt]);
    }
}

__device__ __forceinline__ void gemm_stage_load(
        uint32_t smb, int stage, int tid,
        const s8* __restrict__ Ag, const s8* __restrict__ Bg, int kt){
    uint32_t sA = smb + stage * 32768;
    uint32_t sB = sA + 16384;
#pragma unroll
    for (int p = 0; p < 4; p++){
        int idx = tid + p * 256;
        int r = idx >> 3, seg = idx & 7;
        uint32_t off = r * 128 + ((seg ^ (r & 7)) * 16);
        cpa16(sA + off, Ag + (size_t)r * 768 + kt + seg * 16);
        cpa16(sB + off, Bg + (size_t)r * 768 + kt + seg * 16);
    }
}

// ---------------- QKV GEMM (mma.sync + cp.async pipeline) + LN/quant epilogue ----------------
// grid (18, 128), 256 threads, dyn smem 67584
__global__ void __launch_bounds__(256) k_gemm1(
        const float* __restrict__ qkv_alpha,
        const float* __restrict__ nqw, const float* __restrict__ nqb,
        const float* __restrict__ nkw, const float* __restrict__ nkb){
    extern __shared__ int smw[];
    uint32_t smb = smem_u32(smw);
    int tid = threadIdx.x, lane = tid & 31, wid = tid >> 5;
    int wrBase = (wid >> 2) * 64;
    int wcBase = (wid & 3) * 32;
    int rowBase = blockIdx.y << 7, colBase = blockIdx.x << 7;
    const s8* Ag = g_xq + (size_t)rowBase * 768;
    const s8* Bg = g_wq + (size_t)colBase * 768;

    int acc[4][4][4];
#pragma unroll
    for (int mt = 0; mt < 4; mt++)
#pragma unroll
        for (int nt = 0; nt < 4; nt++)
#pragma unroll
            for (int q = 0; q < 4; q++) acc[mt][nt][q] = 0;

    gemm_stage_load(smb, 0, tid, Ag, Bg, 0);
    CPA_COMMIT();
    for (int kc = 0; kc < 6; kc++){
        if (kc < 5){
            gemm_stage_load(smb, (kc + 1) & 1, tid, Ag, Bg, (kc + 1) * 128);
            CPA_COMMIT();
            CPA_WAIT(1);
        } else {
            CPA_WAIT(0);
        }
        __syncthreads();
        const s8* Atile = (const s8*)smw + (kc & 1) * 32768;
        const s8* Btile = Atile + 16384;
        gemm_stage_compute(Atile, Btile, lane, wrBase, wcBase, acc);
        __syncthreads();
    }

    // stage C tile in smem: [128][132]
    int* Cs = smw;
#pragma unroll
    for (int mt = 0; mt < 4; mt++)
#pragma unroll
        for (int nt = 0; nt < 4; nt++){
            int r0 = wrBase + mt * 16 + (lane >> 2);
            int cl = wcBase + nt * 8 + 2 * (lane & 3);
            Cs[r0 * 132 + cl]           = acc[mt][nt][0];
            Cs[r0 * 132 + cl + 1]       = acc[mt][nt][1];
            Cs[(r0 + 8) * 132 + cl]     = acc[mt][nt][2];
            Cs[(r0 + 8) * 132 + cl + 1] = acc[mt][nt][3];
        }
    __syncthreads();

    float a_in = g_sc[0];
    for (int it = wid; it < 256; it += 8){
        int r = it >> 1, g = it & 1;
        int th = (blockIdx.x << 1) + g;
        int t  = th / 12, h = th - 12 * t;
        int row = rowBase + r;
        int b_ = row >> 9, n = row & 511;
        int d0 = lane * 2;
        int jg = th * 64;
        float al0 = qkv_alpha[jg + d0], al1 = qkv_alpha[jg + d0 + 1];
        float c0 = __fadd_rn((float)Cs[r*132 + g*64 + d0],     g_bi[jg + d0]);
        float c1 = __fadd_rn((float)Cs[r*132 + g*64 + d0 + 1], g_bi[jg + d0 + 1]);
        if (t == 2){
            float va = g_sc[3];
            float ap0 = __fdiv_rn(va, __fmul_rn(a_in, al0));
            float ap1 = __fdiv_rn(va, __fmul_rn(a_in, al1));
            float r0 = fminf(fmaxf(__fdiv_rn(c0, ap0), -4.f), 3.f);
            float r1 = fminf(fmaxf(__fdiv_rn(c1, ap1), -4.f), 3.f);
            s8* dst = g_v2t + (size_t)(b_*12 + h) * 64 * 512;
            dst[(size_t)d0 * 512 + n]       = (s8)(int)rintf(r0);
            dst[(size_t)(d0+1) * 512 + n]   = (s8)(int)rintf(r1);
        } else {
            float xs0 = __fmul_rn(c0, al0), xs1 = __fmul_rn(c1, al1);
            float ssum = warp_sum(__fadd_rn(xs0, xs1));
            float mean = __fdiv_rn(ssum, 64.0f);
            float dv0 = __fadd_rn(xs0, -mean), dv1 = __fadd_rn(xs1, -mean);
            float vs = warp_sum(__fadd_rn(__fmul_rn(dv0, dv0), __fmul_rn(dv1, dv1)));
            float stdv = __fsqrt_rn(__fdiv_rn(vs, 63.0f));
            float den = __fadd_rn(stdv, 1e-5f);
            float xh0 = __fdiv_rn(dv0, den), xh1 = __fdiv_rn(dv1, den);
            const float* w  = (t == 0) ? nqw : nkw;
            const float* bb = (t == 0) ? nqb : nkb;
            float act = (t == 0) ? g_sc[1] : g_sc[2];
            float w0 = w[d0], w1 = w[d0 + 1];
            float alp0 = __fdiv_rn(act, w0), alp1 = __fdiv_rn(act, w1);
            float bi0 = __fdiv_rn(bb[d0], w0), bi1 = __fdiv_rn(bb[d0 + 1], w1);
            float r0 = fminf(fmaxf(__fdiv_rn(__fadd_rn(xh0, bi0), alp0), -4.f), 3.f);
            float r1 = fminf(fmaxf(__fdiv_rn(__fadd_rn(xh1, bi1), alp1), -4.f), 3.f);
            s8* dst = (t == 0) ? g_q2 : g_k2;
            size_t o = ((size_t)(b_*12 + h) * 512 + n) * 64 + d0;
            dst[o]     = (s8)(int)rintf(r0);
            dst[o + 1] = (s8)(int)rintf(r1);
        }
    }
}

// ---------------- attention: EXACT R3 version (proven fast) ----------------
// grid (384, 8), 256 threads, dynamic smem 109824 B
#define DP16(sacc, ar, b0, b1, b2, b3)                   \
    sacc = __dp4a((ar)[0],  (b0).x, sacc); sacc = __dp4a((ar)[1],  (b0).y, sacc); \
    sacc = __dp4a((ar)[2],  (b0).z, sacc); sacc = __dp4a((ar)[3],  (b0).w, sacc); \
    sacc = __dp4a((ar)[4],  (b1).x, sacc); sacc = __dp4a((ar)[5],  (b1).y, sacc); \
    sacc = __dp4a((ar)[6],  (b1).z, sacc); sacc = __dp4a((ar)[7],  (b1).w, sacc); \
    sacc = __dp4a((ar)[8],  (b2).x, sacc); sacc = __dp4a((ar)[9],  (b2).y, sacc); \
    sacc = __dp4a((ar)[10], (b2).z, sacc); sacc = __dp4a((ar)[11], (b2).w, sacc); \
    sacc = __dp4a((ar)[12], (b3).x, sacc); sacc = __dp4a((ar)[13], (b3).y, sacc); \
    sacc = __dp4a((ar)[14], (b3).z, sacc); sacc = __dp4a((ar)[15], (b3).w, sacc)

__global__ void k_attn(){
    extern __shared__ int smw[];
    int*   qs   = smw;                        // 1024 ints
    int*   ks   = smw + 1024;                 // 8192 ints
    int*   vTw  = smw + 9216;                 // 64*132 = 8448 ints
    int*   es   = smw + 17664;                // 64*132 = 8448 ints
    float* rs2  = (float*)(smw + 26112);      // 256
    float* rsum = rs2 + 256;                  // 64
    s8*    lut  = (s8*)(rsum + 64);           // 64 x 64

    int tid = threadIdx.x;
    int bh = blockIdx.x, qt = blockIdx.y;
    size_t base = (size_t)bh * 512 * 64;

    const int4* qg = (const int4*)(g_q2 + base + (size_t)qt * 64 * 64);
    ((int4*)qs)[tid] = qg[tid];
    const int4* kg = (const int4*)(g_k2 + base);
#pragma unroll
    for (int i = tid; i < 2048; i += 256) ((int4*)ks)[i] = kg[i];
    const int4* vg = (const int4*)(g_v2t + base);
#pragma unroll
    for (int i = tid; i < 2048; i += 256){
        int d = i >> 5, seg = i & 31;
        ((int4*)&vTw[d * 132])[seg] = vg[i];
    }
    __syncthreads();

    int qi = tid >> 2, qr = tid & 3;
    int areg[16];
#pragma unroll
    for (int w = 0; w < 16; w++) areg[w] = qs[qi * 16 + w];

    float cs1 = g_sc[6];
    float psum = 0.f;
    int packed = 0;
    for (int i = 0; i < 128; i++){
        int ki = qr * 128 + i;
        const int4* kr = (const int4*)&ks[ki * 16];
        int4 b0 = kr[0], b1 = kr[1], b2 = kr[2], b3 = kr[3];
        int s = 0;
        DP16(s, areg, b0, b1, b2, b3);
        float e = truncf(__fmul_rn(__fmul_rn(cs1, (float)s), 128.0f));
        int ei = (int)rintf(__fmul_rn(e, 0.0078125f));
        psum = __fadd_rn(psum, p2i(ei));
        packed |= (ei & 0xff) << ((i & 3) * 8);
        if ((i & 3) == 3){ es[qi * 132 + (ki >> 2)] = packed; packed = 0; }
    }
    rs2[qi * 4 + qr] = psum;
    __syncthreads();
    if (tid < 64){
        float s = __fadd_rn(__fadd_rn(__fadd_rn(rs2[tid*4], rs2[tid*4+1]), rs2[tid*4+2]), rs2[tid*4+3]);
        rsum[tid] = s;
    }
    __syncthreads();

    float aa = g_sc[4];
    for (int w = tid; w < 4096; w += 256){
        int row = w >> 6, j = w & 63;
        float p = p2i(j - 32);
        float su = rsum[row];
        float r = fminf(fmaxf(__fdiv_rn(__fdiv_rn(p, su), aa), 0.f), 7.f);
        lut[w] = (s8)(int)rintf(r);
    }
    __syncthreads();

    for (int w = tid; w < 8192; w += 256){
        int q2i = w >> 7, k4 = w & 127;
        int e4 = es[q2i * 132 + k4];
        const s8* lr = lut + (q2i << 6);
        int out = 0;
#pragma unroll
        for (int b = 0; b < 4; b++){
            int ei = (int)(s8)(e4 >> (b * 8));
            int j = min(max(ei + 32, 0), 63);
            out |= ((int)lr[j]) << (b * 8);
        }
        es[q2i * 132 + k4] = out;
    }
    __syncthreads();

    int acc[16];
#pragma unroll
    for (int dd = 0; dd < 16; dd++) acc[dd] = 0;
#pragma unroll
    for (int c = 0; c < 8; c++){
        int aw[16];
#pragma unroll
        for (int w = 0; w < 16; w++) aw[w] = es[qi * 132 + c * 16 + w];
#pragma unroll
        for (int dd = 0; dd < 16; dd++){
            int d = qr + 4 * dd;
            const int4* vr = (const int4*)&vTw[d * 132 + c * 16];
            int4 v0 = vr[0], v1 = vr[1], v2 = vr[2], v3 = vr[3];
            int s = acc[dd];
            DP16(s, aw, v0, v1, v2, v3);
            acc[dd] = s;
        }
    }
    float apx = g_sc[7];
    int b_ = bh / 12, h = bh - 12 * b_;
    int row = b_ * 512 + qt * 64 + qi;
    s8* dst = g_x1 + (size_t)row * 768 + h * 64;
#pragma unroll
    for (int dd = 0; dd < 16; dd++){
        float r = fminf(fmaxf(__fdiv_rn((float)acc[dd], apx), -4.f), 3.f);
        dst[qr + 4 * dd] = (s8)(int)rintf(r);
    }
}

// ---------------- projection GEMM (mma.sync + cp.async pipeline) ----------------
// grid (6, 128), 256 threads, dyn smem 65536
__global__ void __launch_bounds__(256) k_gemm2(
        const float* __restrict__ palpha, const float* __restrict__ pbias,
        float* __restrict__ out){
    extern __shared__ int smw[];
    uint32_t smb = smem_u32(smw);
    int tid = threadIdx.x, lane = tid & 31, wid = tid >> 5;
    int wrBase = (wid >> 2) * 64;
    int wcBase = (wid & 3) * 32;
    int rowBase = blockIdx.y << 7, colBase = blockIdx.x << 7;
    const s8* Ag = g_x1 + (size_t)rowBase * 768;
    const s8* Bg = g_pw + (size_t)colBase * 768;

    int acc[4][4][4];
#pragma unroll
    for (int mt = 0; mt < 4; mt++)
#pragma unroll
        for (int nt = 0; nt < 4; nt++)
#pragma unroll
            for (int q = 0; q < 4; q++) acc[mt][nt][q] = 0;

    gemm_stage_load(smb, 0, tid, Ag, Bg, 0);
    CPA_COMMIT();
    for (int kc = 0; kc < 6; kc++){
        if (kc < 5){
            gemm_stage_load(smb, (kc + 1) & 1, tid, Ag, Bg, (kc + 1) * 128);
            CPA_COMMIT();
            CPA_WAIT(1);
        } else {
            CPA_WAIT(0);
        }
        __syncthreads();
        const s8* Atile = (const s8*)smw + (kc & 1) * 32768;
        const s8* Btile = Atile + 16384;
        gemm_stage_compute(Atile, Btile, lane, wrBase, wcBase, acc);
        __syncthreads();
    }

    float pa = g_sc[5];
#pragma unroll
    for (int mt = 0; mt < 4; mt++)
#pragma unroll
        for (int nt = 0; nt < 4; nt++){
            int r0 = rowBase + wrBase + mt * 16 + (lane >> 2);
            int c  = colBase + wcBase + nt * 8 + 2 * (lane & 3);
            float al0 = palpha[c], al1 = palpha[c + 1];
            float bi0 = pbias[c],  bi1 = pbias[c + 1];
            out[(size_t)r0 * 768 + c]
                = __fadd_rn(__fmul_rn(__fmul_rn((float)acc[mt][nt][0], al0), pa), bi0);
            out[(size_t)r0 * 768 + c + 1]
                = __fadd_rn(__fmul_rn(__fmul_rn((float)acc[mt][nt][1], al1), pa), bi1);
            out[(size_t)(r0 + 8) * 768 + c]
                = __fadd_rn(__fmul_rn(__fmul_rn((float)acc[mt][nt][2], al0), pa), bi0);
            out[(size_t)(r0 + 8) * 768 + c + 1]
                = __fadd_rn(__fmul_rn(__fmul_rn((float)acc[mt][nt][3], al1), pa), bi1);
        }
}

// ---------------- launch ----------------
extern "C" void kernel_launch(void* const* d_in, const int* in_sizes, int n_in,
                              void* d_out, int out_size){
    const float* x0          = (const float*)d_in[0];
    const float* qkv_w       = (const float*)d_in[1];
    const float* qkv_alpha   = (const float*)d_in[2];
    const float* qkv_bias    = (const float*)d_in[3];
    const float* qkv_act_al  = (const float*)d_in[4];
    const float* proj_w      = (const float*)d_in[5];
    const float* proj_alpha  = (const float*)d_in[6];
    const float* proj_bias   = (const float*)d_in[7];
    const float* proj_act_al = (const float*)d_in[8];
    const float* normq_w     = (const float*)d_in[9];
    const float* normq_b     = (const float*)d_in[10];
    const float* normk_w     = (const float*)d_in[11];
    const float* normk_b     = (const float*)d_in[12];
    const float* qact        = (const float*)d_in[13];
    const float* kact        = (const float*)d_in[14];
    const float* vact        = (const float*)d_in[15];
    const float* attnact     = (const float*)d_in[16];
    float* out = (float*)d_out;

    cudaFuncSetAttribute(k_gemm1, cudaFuncAttributeMaxDynamicSharedMemorySize, 67584);
    cudaFuncSetAttribute(k_gemm2, cudaFuncAttributeMaxDynamicSharedMemorySize, 65536);
    cudaFuncSetAttribute(k_attn,  cudaFuncAttributeMaxDynamicSharedMemorySize, 109824);

    // k_attn is our 4th launch -> lands in the ncu capture slot next round
    k_scalars<<<1, 256>>>(qkv_act_al, qact, kact, vact, attnact, proj_act_al,
                          qkv_bias, qkv_alpha);
    k_quant_xw<<<4800, 256>>>(x0, qkv_w, qkv_alpha);
    k_gemm1<<<dim3(18, 128), 256, 67584>>>(qkv_alpha, normq_w, normq_b, normk_w, normk_b);
    k_attn<<<dim3(384, 8), 256, 109824>>>();
    k_quant_pw<<<576, 256>>>(proj_w, proj_alpha);
    k_gemm2<<<dim3(6, 128), 256, 65536>>>(proj_alpha, proj_bias, out);
}

// round 9
// speedup vs baseline: 1.5025x; 1.4205x over previous
#include <cuda_runtime.h>
#include <cstdint>
#include <cstddef>

#define BB 32
#define NN 512
#define CC 768
#define HH 12
#define HD 64
#define MTOT (BB*NN)      // 16384
#define NC3 (3*CC)        // 2304

typedef signed char s8;

// ---------------- device scratch (allocation-free) ----------------
__device__ float g_sc[8]; // 0:a_in 1:qa 2:ka 3:va 4:aa 5:pa 6:cs1 7:apx
__device__ s8    g_xq[MTOT*CC];
__device__ s8    g_wq[NC3*CC];
__device__ float g_bi[NC3];
__device__ s8    g_q2[BB*HH*NN*HD];
__device__ s8    g_k2[BB*HH*NN*HD];
__device__ s8    g_v2t[BB*HH*HD*NN];   // [bh][d][n]
__device__ s8    g_x1[MTOT*CC];
__device__ s8    g_pw[CC*CC];

__device__ __forceinline__ float warp_sum(float v){
#pragma unroll
    for (int o = 16; o > 0; o >>= 1)
        v = __fadd_rn(v, __shfl_xor_sync(0xffffffffu, v, o));
    return v;
}

__device__ __forceinline__ s8 q_rc(float v, float a, float lo, float hi){
    float r = __fdiv_rn(v, a);
    r = fminf(fmaxf(r, lo), hi);
    return (s8)(int)rintf(r);
}

// exact 2^ei for integer ei >= -126
__device__ __forceinline__ float p2i(int ei){
    int ec = max(ei, -126);
    return __int_as_float((ec + 127) << 23);
}

__device__ __forceinline__ void mma_s8(int* d, const int* a, const int* b){
    asm volatile(
        "mma.sync.aligned.m16n8k32.row.col.s32.s8.s8.s32 "
        "{%0,%1,%2,%3}, {%4,%5,%6,%7}, {%8,%9}, {%0,%1,%2,%3};"
        : "+r"(d[0]), "+r"(d[1]), "+r"(d[2]), "+r"(d[3])
        : "r"(a[0]), "r"(a[1]), "r"(a[2]), "r"(a[3]), "r"(b[0]), "r"(b[1]));
}

__device__ __forceinline__ uint32_t smem_u32(const void* p){
    uint32_t a;
    asm("{ .reg .u64 t; cvta.to.shared.u64 t, %1; cvt.u32.u64 %0, t; }" : "=r"(a) : "l"(p));
    return a;
}
__device__ __forceinline__ void cpa16(uint32_t dst, const void* src){
    asm volatile("cp.async.ca.shared.global [%0], [%1], 16;" :: "r"(dst), "l"(src));
}
#define CPA_COMMIT() asm volatile("cp.async.commit_group;" ::: "memory")
#define CPA_WAIT(n)  asm volatile("cp.async.wait_group %0;" :: "n"(n) : "memory")

// ---------------- scalar means + integer bias ----------------
__global__ void k_scalars(const float* __restrict__ qaa, const float* __restrict__ qact,
                          const float* __restrict__ kact, const float* __restrict__ vact,
                          const float* __restrict__ aact, const float* __restrict__ paa,
                          const float* __restrict__ qkv_bias, const float* __restrict__ qkv_alpha){
    int tid = threadIdx.x;
    if (tid < 32){
        int lane = tid;
        float s = 0.f;
        for (int i = lane; i < 768; i += 32) s = __fadd_rn(s, qaa[i]);
        float a_in = __fdiv_rn(warp_sum(s), 768.0f);
        s = 0.f;
        for (int i = lane; i < 768; i += 32) s = __fadd_rn(s, paa[i]);
        float pa = __fdiv_rn(warp_sum(s), 768.0f);
        float t;
        t = (lane < 12) ? qact[lane] : 0.f; float qa = __fdiv_rn(warp_sum(t), 12.0f);
        t = (lane < 12) ? kact[lane] : 0.f; float ka = __fdiv_rn(warp_sum(t), 12.0f);
        t = (lane < 12) ? vact[lane] : 0.f; float va = __fdiv_rn(warp_sum(t), 12.0f);
        t = (lane < 12) ? aact[lane] : 0.f; float aa = __fdiv_rn(warp_sum(t), 12.0f);
        if (lane == 0){
            g_sc[0] = a_in; g_sc[1] = qa; g_sc[2] = ka; g_sc[3] = va; g_sc[4] = aa; g_sc[5] = pa;
            float sm = __fmul_rn(__fmul_rn(0.125f, qa), ka);
            g_sc[6] = __fmul_rn(1.4426950408889634f, sm);
            g_sc[7] = __fdiv_rn(pa, __fmul_rn(aa, va));
        }
    }
    __syncthreads();
    float a_in = g_sc[0];
    for (int j = tid; j < NC3; j += 256)
        g_bi[j] = truncf(__fdiv_rn(__fdiv_rn(qkv_bias[j], a_in), qkv_alpha[j]));
}

// ---------------- fused input+weight quantization ----------------
__global__ void k_quant_xw(const float* __restrict__ x, const float* __restrict__ w,
                           const float* __restrict__ al){
    if (blockIdx.x < 3072){
        float a = g_sc[0];
        int base = blockIdx.x * 1024 + threadIdx.x;
#pragma unroll
        for (int p = 0; p < 4; p++){
            int idx = base + p * 256;
            float4 v = ((const float4*)x)[idx];
            char4 c;
            c.x = q_rc(v.x, a, -8.f, 7.f); c.y = q_rc(v.y, a, -8.f, 7.f);
            c.z = q_rc(v.z, a, -8.f, 7.f); c.w = q_rc(v.w, a, -8.f, 7.f);
            ((char4*)g_xq)[idx] = c;
        }
    } else {
        int idx = (blockIdx.x - 3072) * 256 + threadIdx.x;
        int row = idx / 192;
        float a = al[row];
        float4 v = ((const float4*)w)[idx];
        char4 c;
        c.x = q_rc(v.x, a, -8.f, 7.f); c.y = q_rc(v.y, a, -8.f, 7.f);
        c.z = q_rc(v.z, a, -8.f, 7.f); c.w = q_rc(v.w, a, -8.f, 7.f);
        ((char4*)g_wq)[idx] = c;
    }
}

__global__ void k_quant_pw(const float* __restrict__ w, const float* __restrict__ al){
    int idx = blockIdx.x * 256 + threadIdx.x;
    int row = idx / 192;
    float a = al[row];
    float4 v = ((const float4*)w)[idx];
    char4 c;
    c.x = q_rc(v.x, a, -8.f, 7.f); c.y = q_rc(v.y, a, -8.f, 7.f);
    c.z = q_rc(v.z, a, -8.f, 7.f); c.w = q_rc(v.w, a, -8.f, 7.f);
    ((char4*)g_pw)[idx] = c;
}

// ---------------- GEMM compute tile (shared by gemm1/gemm2) ----------------
__device__ __forceinline__ void gemm_stage_compute(
        const s8* Atile, const s8* Btile, int lane, int wrBase, int wcBase,
        int acc[4][4][4]){
#pragma unroll
    for (int s = 0; s < 4; s++){
        int c4 = (lane & 3) * 4;
        int afr[4][4];
#pragma unroll
        for (int mt = 0; mt < 4; mt++){
            int r0 = wrBase + mt * 16 + (lane >> 2);
            int r1 = r0 + 8;
            afr[mt][0] = *(const int*)(Atile + r0*128 + (((2*s  ) ^ (r0 & 7)) * 16) + c4);
            afr[mt][1] = *(const int*)(Atile + r1*128 + (((2*s  ) ^ (r1 & 7)) * 16) + c4);
            afr[mt][2] = *(const int*)(Atile + r0*128 + (((2*s+1) ^ (r0 & 7)) * 16) + c4);
            afr[mt][3] = *(const int*)(Atile + r1*128 + (((2*s+1) ^ (r1 & 7)) * 16) + c4);
        }
        int bfr[4][2];
#pragma unroll
        for (int nt = 0; nt < 4; nt++){
            int c0 = wcBase + nt * 8 + (lane >> 2);
            bfr[nt][0] = *(const int*)(Btile + c0*128 + (((2*s  ) ^ (c0 & 7)) * 16) + c4);
            bfr[nt][1] = *(const int*)(Btile + c0*128 + (((2*s+1) ^ (c0 & 7)) * 16) + c4);
        }
#pragma unroll
        for (int mt = 0; mt < 4; mt++)
#pragma unroll
            for (int nt = 0; nt < 4; nt++)
                mma_s8(acc[mt][nt], afr[mt], bfr[nt]);
    }
}

__device__ __forceinline__ void gemm_stage_load(
        uint32_t smb, int stage, int tid,
        const s8* __restrict__ Ag, const s8* __restrict__ Bg, int kt){
    uint32_t sA = smb + stage * 32768;
    uint32_t sB = sA + 16384;
#pragma unroll
    for (int p = 0; p < 4; p++){
        int idx = tid + p * 256;
        int r = idx >> 3, seg = idx & 7;
        uint32_t off = r * 128 + ((seg ^ (r & 7)) * 16);
        cpa16(sA + off, Ag + (size_t)r * 768 + kt + seg * 16);
        cpa16(sB + off, Bg + (size_t)r * 768 + kt + seg * 16);
    }
}

// ---------------- QKV GEMM (mma.sync + cp.async pipeline) + LN/quant epilogue ----------------
// grid (18, 128), 256 threads, dyn smem 67584
__global__ void __launch_bounds__(256) k_gemm1(
        const float* __restrict__ qkv_alpha,
        const float* __restrict__ nqw, const float* __restrict__ nqb,
        const float* __restrict__ nkw, const float* __restrict__ nkb){
    extern __shared__ int smw[];
    uint32_t smb = smem_u32(smw);
    int tid = threadIdx.x, lane = tid & 31, wid = tid >> 5;
    int wrBase = (wid >> 2) * 64;
    int wcBase = (wid & 3) * 32;
    int rowBase = blockIdx.y << 7, colBase = blockIdx.x << 7;
    const s8* Ag = g_xq + (size_t)rowBase * 768;
    const s8* Bg = g_wq + (size_t)colBase * 768;

    int acc[4][4][4];
#pragma unroll
    for (int mt = 0; mt < 4; mt++)
#pragma unroll
        for (int nt = 0; nt < 4; nt++)
#pragma unroll
            for (int q = 0; q < 4; q++) acc[mt][nt][q] = 0;

    gemm_stage_load(smb, 0, tid, Ag, Bg, 0);
    CPA_COMMIT();
    for (int kc = 0; kc < 6; kc++){
        if (kc < 5){
            gemm_stage_load(smb, (kc + 1) & 1, tid, Ag, Bg, (kc + 1) * 128);
            CPA_COMMIT();
            CPA_WAIT(1);
        } else {
            CPA_WAIT(0);
        }
        __syncthreads();
        const s8* Atile = (const s8*)smw + (kc & 1) * 32768;
        const s8* Btile = Atile + 16384;
        gemm_stage_compute(Atile, Btile, lane, wrBase, wcBase, acc);
        __syncthreads();
    }

    // stage C tile in smem: [128][132]
    int* Cs = smw;
#pragma unroll
    for (int mt = 0; mt < 4; mt++)
#pragma unroll
        for (int nt = 0; nt < 4; nt++){
            int r0 = wrBase + mt * 16 + (lane >> 2);
            int cl = wcBase + nt * 8 + 2 * (lane & 3);
            Cs[r0 * 132 + cl]           = acc[mt][nt][0];
            Cs[r0 * 132 + cl + 1]       = acc[mt][nt][1];
            Cs[(r0 + 8) * 132 + cl]     = acc[mt][nt][2];
            Cs[(r0 + 8) * 132 + cl + 1] = acc[mt][nt][3];
        }
    __syncthreads();

    float a_in = g_sc[0];
    for (int it = wid; it < 256; it += 8){
        int r = it >> 1, g = it & 1;
        int th = (blockIdx.x << 1) + g;
        int t  = th / 12, h = th - 12 * t;
        int row = rowBase + r;
        int b_ = row >> 9, n = row & 511;
        int d0 = lane * 2;
        int jg = th * 64;
        float al0 = qkv_alpha[jg + d0], al1 = qkv_alpha[jg + d0 + 1];
        float c0 = __fadd_rn((float)Cs[r*132 + g*64 + d0],     g_bi[jg + d0]);
        float c1 = __fadd_rn((float)Cs[r*132 + g*64 + d0 + 1], g_bi[jg + d0 + 1]);
        if (t == 2){
            float va = g_sc[3];
            float ap0 = __fdiv_rn(va, __fmul_rn(a_in, al0));
            float ap1 = __fdiv_rn(va, __fmul_rn(a_in, al1));
            float r0 = fminf(fmaxf(__fdiv_rn(c0, ap0), -4.f), 3.f);
            float r1 = fminf(fmaxf(__fdiv_rn(c1, ap1), -4.f), 3.f);
            s8* dst = g_v2t + (size_t)(b_*12 + h) * 64 * 512;
            dst[(size_t)d0 * 512 + n]       = (s8)(int)rintf(r0);
            dst[(size_t)(d0+1) * 512 + n]   = (s8)(int)rintf(r1);
        } else {
            float xs0 = __fmul_rn(c0, al0), xs1 = __fmul_rn(c1, al1);
            float ssum = warp_sum(__fadd_rn(xs0, xs1));
            float mean = __fdiv_rn(ssum, 64.0f);
            float dv0 = __fadd_rn(xs0, -mean), dv1 = __fadd_rn(xs1, -mean);
            float vs = warp_sum(__fadd_rn(__fmul_rn(dv0, dv0), __fmul_rn(dv1, dv1)));
            float stdv = __fsqrt_rn(__fdiv_rn(vs, 63.0f));
            float den = __fadd_rn(stdv, 1e-5f);
            float xh0 = __fdiv_rn(dv0, den), xh1 = __fdiv_rn(dv1, den);
            const float* w  = (t == 0) ? nqw : nkw;
            const float* bb = (t == 0) ? nqb : nkb;
            float act = (t == 0) ? g_sc[1] : g_sc[2];
            float w0 = w[d0], w1 = w[d0 + 1];
            float alp0 = __fdiv_rn(act, w0), alp1 = __fdiv_rn(act, w1);
            float bi0 = __fdiv_rn(bb[d0], w0), bi1 = __fdiv_rn(bb[d0 + 1], w1);
            float r0 = fminf(fmaxf(__fdiv_rn(__fadd_rn(xh0, bi0), alp0), -4.f), 3.f);
            float r1 = fminf(fmaxf(__fdiv_rn(__fadd_rn(xh1, bi1), alp1), -4.f), 3.f);
            s8* dst = (t == 0) ? g_q2 : g_k2;
            size_t o = ((size_t)(b_*12 + h) * 512 + n) * 64 + d0;
            dst[o]     = (s8)(int)rintf(r0);
            dst[o + 1] = (s8)(int)rintf(r1);
        }
    }
}

// ---------------- attention: R3 structure + K-row bank-stagger fix ----------------
// grid (384, 8), 256 threads, dynamic smem 109888 B
// K row ki stored at int offset ki*16 + (ki>>7)*4  -> qr quadrants land on
// distinct bank groups (was: 8192B apart = identical banks = 4-way conflict)
#define DP16(sacc, ar, b0, b1, b2, b3)                   \
    sacc = __dp4a((ar)[0],  (b0).x, sacc); sacc = __dp4a((ar)[1],  (b0).y, sacc); \
    sacc = __dp4a((ar)[2],  (b0).z, sacc); sacc = __dp4a((ar)[3],  (b0).w, sacc); \
    sacc = __dp4a((ar)[4],  (b1).x, sacc); sacc = __dp4a((ar)[5],  (b1).y, sacc); \
    sacc = __dp4a((ar)[6],  (b1).z, sacc); sacc = __dp4a((ar)[7],  (b1).w, sacc); \
    sacc = __dp4a((ar)[8],  (b2).x, sacc); sacc = __dp4a((ar)[9],  (b2).y, sacc); \
    sacc = __dp4a((ar)[10], (b2).z, sacc); sacc = __dp4a((ar)[11], (b2).w, sacc); \
    sacc = __dp4a((ar)[12], (b3).x, sacc); sacc = __dp4a((ar)[13], (b3).y, sacc); \
    sacc = __dp4a((ar)[14], (b3).z, sacc); sacc = __dp4a((ar)[15], (b3).w, sacc)

__global__ void k_attn(){
    extern __shared__ int smw[];
    int*   qs   = smw;                        // 1024 ints
    int*   ks   = smw + 1024;                 // 8208 ints (staggered rows)
    int*   vTw  = smw + 9232;                 // 64*132 = 8448 ints
    int*   es   = smw + 17680;                // 64*132 = 8448 ints
    float* rs2  = (float*)(smw + 26128);      // 256
    float* rsum = rs2 + 256;                  // 64
    s8*    lut  = (s8*)(rsum + 64);           // 64 x 64

    int tid = threadIdx.x;
    int bh = blockIdx.x, qt = blockIdx.y;
    size_t base = (size_t)bh * 512 * 64;

    const int4* qg = (const int4*)(g_q2 + base + (size_t)qt * 64 * 64);
    ((int4*)qs)[tid] = qg[tid];
    const int4* kg = (const int4*)(g_k2 + base);
#pragma unroll
    for (int i = tid; i < 2048; i += 256){
        int ki = i >> 2, seg = i & 3;
        *(int4*)&ks[ki * 16 + (ki >> 7) * 4 + seg * 4] = kg[i];
    }
    const int4* vg = (const int4*)(g_v2t + base);
#pragma unroll
    for (int i = tid; i < 2048; i += 256){
        int d = i >> 5, seg = i & 31;
        ((int4*)&vTw[d * 132])[seg] = vg[i];
    }
    __syncthreads();

    int qi = tid >> 2, qr = tid & 3;
    int areg[16];
#pragma unroll
    for (int w = 0; w < 16; w++) areg[w] = qs[qi * 16 + w];

    float cs1 = g_sc[6];
    float psum = 0.f;
    int packed = 0;
    const int* ksq = ks + qr * (2048 + 4);   // qr*128 rows * 16 ints + qr*4 stagger
    for (int i = 0; i < 128; i++){
        const int4* kr = (const int4*)(ksq + i * 16);
        int4 b0 = kr[0], b1 = kr[1], b2 = kr[2], b3 = kr[3];
        int s = 0;
        DP16(s, areg, b0, b1, b2, b3);
        float e = truncf(__fmul_rn(__fmul_rn(cs1, (float)s), 128.0f));
        int ei = (int)rintf(__fmul_rn(e, 0.0078125f));
        psum = __fadd_rn(psum, p2i(ei));
        packed |= (ei & 0xff) << ((i & 3) * 8);
        if ((i & 3) == 3){ es[qi * 132 + ((qr * 128 + i) >> 2)] = packed; packed = 0; }
    }
    rs2[qi * 4 + qr] = psum;
    __syncthreads();
    if (tid < 64){
        float s = __fadd_rn(__fadd_rn(__fadd_rn(rs2[tid*4], rs2[tid*4+1]), rs2[tid*4+2]), rs2[tid*4+3]);
        rsum[tid] = s;
    }
    __syncthreads();

    float aa = g_sc[4];
    for (int w = tid; w < 4096; w += 256){
        int row = w >> 6, j = w & 63;
        float p = p2i(j - 32);
        float su = rsum[row];
        float r = fminf(fmaxf(__fdiv_rn(__fdiv_rn(p, su), aa), 0.f), 7.f);
        lut[w] = (s8)(int)rintf(r);
    }
    __syncthreads();

    for (int w = tid; w < 8192; w += 256){
        int q2i = w >> 7, k4 = w & 127;
        int e4 = es[q2i * 132 + k4];
        const s8* lr = lut + (q2i << 6);
        int out = 0;
#pragma unroll
        for (int b = 0; b < 4; b++){
            int ei = (int)(s8)(e4 >> (b * 8));
            int j = min(max(ei + 32, 0), 63);
            out |= ((int)lr[j]) << (b * 8);
        }
        es[q2i * 132 + k4] = out;
    }
    __syncthreads();

    int acc[16];
#pragma unroll
    for (int dd = 0; dd < 16; dd++) acc[dd] = 0;
#pragma unroll
    for (int c = 0; c < 8; c++){
        int aw[16];
#pragma unroll
        for (int w = 0; w < 16; w++) aw[w] = es[qi * 132 + c * 16 + w];
#pragma unroll
        for (int dd = 0; dd < 16; dd++){
            int d = qr + 4 * dd;
            const int4* vr = (const int4*)&vTw[d * 132 + c * 16];
            int4 v0 = vr[0], v1 = vr[1], v2 = vr[2], v3 = vr[3];
            int s = acc[dd];
            DP16(s, aw, v0, v1, v2, v3);
            acc[dd] = s;
        }
    }
    float apx = g_sc[7];
    int b_ = bh / 12, h = bh - 12 * b_;
    int row = b_ * 512 + qt * 64 + qi;
    s8* dst = g_x1 + (size_t)row * 768 + h * 64;
#pragma unroll
    for (int dd = 0; dd < 16; dd++){
        float r = fminf(fmaxf(__fdiv_rn((float)acc[dd], apx), -4.f), 3.f);
        dst[qr + 4 * dd] = (s8)(int)rintf(r);
    }
}

// ---------------- projection GEMM (mma.sync + cp.async pipeline) ----------------
// grid (6, 128), 256 threads, dyn smem 65536
__global__ void __launch_bounds__(256) k_gemm2(
        const float* __restrict__ palpha, const float* __restrict__ pbias,
        float* __restrict__ out){
    extern __shared__ int smw[];
    uint32_t smb = smem_u32(smw);
    int tid = threadIdx.x, lane = tid & 31, wid = tid >> 5;
    int wrBase = (wid >> 2) * 64;
    int wcBase = (wid & 3) * 32;
    int rowBase = blockIdx.y << 7, colBase = blockIdx.x << 7;
    const s8* Ag = g_x1 + (size_t)rowBase * 768;
    const s8* Bg = g_pw + (size_t)colBase * 768;

    int acc[4][4][4];
#pragma unroll
    for (int mt = 0; mt < 4; mt++)
#pragma unroll
        for (int nt = 0; nt < 4; nt++)
#pragma unroll
            for (int q = 0; q < 4; q++) acc[mt][nt][q] = 0;

    gemm_stage_load(smb, 0, tid, Ag, Bg, 0);
    CPA_COMMIT();
    for (int kc = 0; kc < 6; kc++){
        if (kc < 5){
            gemm_stage_load(smb, (kc + 1) & 1, tid, Ag, Bg, (kc + 1) * 128);
            CPA_COMMIT();
            CPA_WAIT(1);
        } else {
            CPA_WAIT(0);
        }
        __syncthreads();
        const s8* Atile = (const s8*)smw + (kc & 1) * 32768;
        const s8* Btile = Atile + 16384;
        gemm_stage_compute(Atile, Btile, lane, wrBase, wcBase, acc);
        __syncthreads();
    }

    float pa = g_sc[5];
#pragma unroll
    for (int mt = 0; mt < 4; mt++)
#pragma unroll
        for (int nt = 0; nt < 4; nt++){
            int r0 = rowBase + wrBase + mt * 16 + (lane >> 2);
            int c  = colBase + wcBase + nt * 8 + 2 * (lane & 3);
            float al0 = palpha[c], al1 = palpha[c + 1];
            float bi0 = pbias[c],  bi1 = pbias[c + 1];
            out[(size_t)r0 * 768 + c]
                = __fadd_rn(__fmul_rn(__fmul_rn((float)acc[mt][nt][0], al0), pa), bi0);
            out[(size_t)r0 * 768 + c + 1]
                = __fadd_rn(__fmul_rn(__fmul_rn((float)acc[mt][nt][1], al1), pa), bi1);
            out[(size_t)(r0 + 8) * 768 + c]
                = __fadd_rn(__fmul_rn(__fmul_rn((float)acc[mt][nt][2], al0), pa), bi0);
            out[(size_t)(r0 + 8) * 768 + c + 1]
                = __fadd_rn(__fmul_rn(__fmul_rn((float)acc[mt][nt][3], al1), pa), bi1);
        }
}

// ---------------- launch ----------------
extern "C" void kernel_launch(void* const* d_in, const int* in_sizes, int n_in,
                              void* d_out, int out_size){
    const float* x0          = (const float*)d_in[0];
    const float* qkv_w       = (const float*)d_in[1];
    const float* qkv_alpha   = (const float*)d_in[2];
    const float* qkv_bias    = (const float*)d_in[3];
    const float* qkv_act_al  = (const float*)d_in[4];
    const float* proj_w      = (const float*)d_in[5];
    const float* proj_alpha  = (const float*)d_in[6];
    const float* proj_bias   = (const float*)d_in[7];
    const float* proj_act_al = (const float*)d_in[8];
    const float* normq_w     = (const float*)d_in[9];
    const float* normq_b     = (const float*)d_in[10];
    const float* normk_w     = (const float*)d_in[11];
    const float* normk_b     = (const float*)d_in[12];
    const float* qact        = (const float*)d_in[13];
    const float* kact        = (const float*)d_in[14];
    const float* vact        = (const float*)d_in[15];
    const float* attnact     = (const float*)d_in[16];
    float* out = (float*)d_out;

    cudaFuncSetAttribute(k_gemm1, cudaFuncAttributeMaxDynamicSharedMemorySize, 67584);
    cudaFuncSetAttribute(k_gemm2, cudaFuncAttributeMaxDynamicSharedMemorySize, 65536);
    cudaFuncSetAttribute(k_attn,  cudaFuncAttributeMaxDynamicSharedMemorySize, 109888);

    k_scalars<<<1, 256>>>(qkv_act_al, qact, kact, vact, attnact, proj_act_al,
                          qkv_bias, qkv_alpha);
    k_quant_xw<<<4800, 256>>>(x0, qkv_w, qkv_alpha);
    k_gemm1<<<dim3(18, 128), 256, 67584>>>(qkv_alpha, normq_w, normq_b, normk_w, normk_b);
    k_attn<<<dim3(384, 8), 256, 109888>>>();
    k_quant_pw<<<576, 256>>>(proj_w, proj_alpha);
    k_gemm2<<<dim3(6, 128), 256, 65536>>>(proj_alpha, proj_bias, out);
}

// round 10
// speedup vs baseline: 1.6942x; 1.1275x over previous
#include <cuda_runtime.h>
#include <cstdint>
#include <cstddef>

#define BB 32
#define NN 512
#define CC 768
#define HH 12
#define HD 64
#define MTOT (BB*NN)      // 16384
#define NC3 (3*CC)        // 2304

typedef signed char s8;

// ---------------- device scratch (allocation-free) ----------------
__device__ float g_sc[8]; // 0:a_in 1:qa 2:ka 3:va 4:aa 5:pa 6:cs1 7:apx
__device__ s8    g_xq[MTOT*CC];
__device__ s8    g_wq[NC3*CC];
__device__ float g_bi[NC3];
__device__ s8    g_q2[BB*HH*NN*HD];
__device__ s8    g_k2[BB*HH*NN*HD];
__device__ s8    g_v2t[BB*HH*HD*NN];   // [bh][d][n]
__device__ s8    g_x1[MTOT*CC];
__device__ s8    g_pw[CC*CC];

__device__ __forceinline__ float warp_sum(float v){
#pragma unroll
    for (int o = 16; o > 0; o >>= 1)
        v = __fadd_rn(v, __shfl_xor_sync(0xffffffffu, v, o));
    return v;
}

__device__ __forceinline__ s8 q_rc(float v, float a, float lo, float hi){
    float r = __fdiv_rn(v, a);
    r = fminf(fmaxf(r, lo), hi);
    return (s8)(int)rintf(r);
}

// exact 2^ei for integer ei >= -126
__device__ __forceinline__ float p2i(int ei){
    int ec = max(ei, -126);
    return __int_as_float((ec + 127) << 23);
}

__device__ __forceinline__ void mma_s8(int* d, const int* a, const int* b){
    asm volatile(
        "mma.sync.aligned.m16n8k32.row.col.s32.s8.s8.s32 "
        "{%0,%1,%2,%3}, {%4,%5,%6,%7}, {%8,%9}, {%0,%1,%2,%3};"
        : "+r"(d[0]), "+r"(d[1]), "+r"(d[2]), "+r"(d[3])
        : "r"(a[0]), "r"(a[1]), "r"(a[2]), "r"(a[3]), "r"(b[0]), "r"(b[1]));
}

__device__ __forceinline__ uint32_t smem_u32(const void* p){
    uint32_t a;
    asm("{ .reg .u64 t; cvta.to.shared.u64 t, %1; cvt.u32.u64 %0, t; }" : "=r"(a) : "l"(p));
    return a;
}
__device__ __forceinline__ void cpa16(uint32_t dst, const void* src){
    asm volatile("cp.async.ca.shared.global [%0], [%1], 16;" :: "r"(dst), "l"(src));
}
#define CPA_COMMIT() asm volatile("cp.async.commit_group;" ::: "memory")
#define CPA_WAIT(n)  asm volatile("cp.async.wait_group %0;" :: "n"(n) : "memory")

// ---------------- scalar means + integer bias ----------------
__global__ void k_scalars(const float* __restrict__ qaa, const float* __restrict__ qact,
                          const float* __restrict__ kact, const float* __restrict__ vact,
                          const float* __restrict__ aact, const float* __restrict__ paa,
                          const float* __restrict__ qkv_bias, const float* __restrict__ qkv_alpha){
    int tid = threadIdx.x;
    if (tid < 32){
        int lane = tid;
        float s = 0.f;
        for (int i = lane; i < 768; i += 32) s = __fadd_rn(s, qaa[i]);
        float a_in = __fdiv_rn(warp_sum(s), 768.0f);
        s = 0.f;
        for (int i = lane; i < 768; i += 32) s = __fadd_rn(s, paa[i]);
        float pa = __fdiv_rn(warp_sum(s), 768.0f);
        float t;
        t = (lane < 12) ? qact[lane] : 0.f; float qa = __fdiv_rn(warp_sum(t), 12.0f);
        t = (lane < 12) ? kact[lane] : 0.f; float ka = __fdiv_rn(warp_sum(t), 12.0f);
        t = (lane < 12) ? vact[lane] : 0.f; float va = __fdiv_rn(warp_sum(t), 12.0f);
        t = (lane < 12) ? aact[lane] : 0.f; float aa = __fdiv_rn(warp_sum(t), 12.0f);
        if (lane == 0){
            g_sc[0] = a_in; g_sc[1] = qa; g_sc[2] = ka; g_sc[3] = va; g_sc[4] = aa; g_sc[5] = pa;
            float sm = __fmul_rn(__fmul_rn(0.125f, qa), ka);
            g_sc[6] = __fmul_rn(1.4426950408889634f, sm);
            g_sc[7] = __fdiv_rn(pa, __fmul_rn(aa, va));
        }
    }
    __syncthreads();
    float a_in = g_sc[0];
    for (int j = tid; j < NC3; j += 256)
        g_bi[j] = truncf(__fdiv_rn(__fdiv_rn(qkv_bias[j], a_in), qkv_alpha[j]));
}

// ---------------- fused input+weight quantization ----------------
__global__ void k_quant_xw(const float* __restrict__ x, const float* __restrict__ w,
                           const float* __restrict__ al){
    if (blockIdx.x < 3072){
        float a = g_sc[0];
        int base = blockIdx.x * 1024 + threadIdx.x;
#pragma unroll
        for (int p = 0; p < 4; p++){
            int idx = base + p * 256;
            float4 v = ((const float4*)x)[idx];
            char4 c;
            c.x = q_rc(v.x, a, -8.f, 7.f); c.y = q_rc(v.y, a, -8.f, 7.f);
            c.z = q_rc(v.z, a, -8.f, 7.f); c.w = q_rc(v.w, a, -8.f, 7.f);
            ((char4*)g_xq)[idx] = c;
        }
    } else {
        int idx = (blockIdx.x - 3072) * 256 + threadIdx.x;
        int row = idx / 192;
        float a = al[row];
        float4 v = ((const float4*)w)[idx];
        char4 c;
        c.x = q_rc(v.x, a, -8.f, 7.f); c.y = q_rc(v.y, a, -8.f, 7.f);
        c.z = q_rc(v.z, a, -8.f, 7.f); c.w = q_rc(v.w, a, -8.f, 7.f);
        ((char4*)g_wq)[idx] = c;
    }
}

__global__ void k_quant_pw(const float* __restrict__ w, const float* __restrict__ al){
    int idx = blockIdx.x * 256 + threadIdx.x;
    int row = idx / 192;
    float a = al[row];
    float4 v = ((const float4*)w)[idx];
    char4 c;
    c.x = q_rc(v.x, a, -8.f, 7.f); c.y = q_rc(v.y, a, -8.f, 7.f);
    c.z = q_rc(v.z, a, -8.f, 7.f); c.w = q_rc(v.w, a, -8.f, 7.f);
    ((char4*)g_pw)[idx] = c;
}

// ---------------- GEMM compute tile (shared by gemm1/gemm2) ----------------
__device__ __forceinline__ void gemm_stage_compute(
        const s8* Atile, const s8* Btile, int lane, int wrBase, int wcBase,
        int acc[4][4][4]){
#pragma unroll
    for (int s = 0; s < 4; s++){
        int c4 = (lane & 3) * 4;
        int afr[4][4];
#pragma unroll
        for (int mt = 0; mt < 4; mt++){
            int r0 = wrBase + mt * 16 + (lane >> 2);
            int r1 = r0 + 8;
            afr[mt][0] = *(const int*)(Atile + r0*128 + (((2*s  ) ^ (r0 & 7)) * 16) + c4);
            afr[mt][1] = *(const int*)(Atile + r1*128 + (((2*s  ) ^ (r1 & 7)) * 16) + c4);
            afr[mt][2] = *(const int*)(Atile + r0*128 + (((2*s+1) ^ (r0 & 7)) * 16) + c4);
            afr[mt][3] = *(const int*)(Atile + r1*128 + (((2*s+1) ^ (r1 & 7)) * 16) + c4);
        }
        int bfr[4][2];
#pragma unroll
        for (int nt = 0; nt < 4; nt++){
            int c0 = wcBase + nt * 8 + (lane >> 2);
            bfr[nt][0] = *(const int*)(Btile + c0*128 + (((2*s  ) ^ (c0 & 7)) * 16) + c4);
            bfr[nt][1] = *(const int*)(Btile + c0*128 + (((2*s+1) ^ (c0 & 7)) * 16) + c4);
        }
#pragma unroll
        for (int mt = 0; mt < 4; mt++)
#pragma unroll
            for (int nt = 0; nt < 4; nt++)
                mma_s8(acc[mt][nt], afr[mt], bfr[nt]);
    }
}

__device__ __forceinline__ void gemm_stage_load(
        uint32_t smb, int stage, int tid,
        const s8* __restrict__ Ag, const s8* __restrict__ Bg, int kt){
    uint32_t sA = smb + stage * 32768;
    uint32_t sB = sA + 16384;
#pragma unroll
    for (int p = 0; p < 4; p++){
        int idx = tid + p * 256;
        int r = idx >> 3, seg = idx & 7;
        uint32_t off = r * 128 + ((seg ^ (r & 7)) * 16);
        cpa16(sA + off, Ag + (size_t)r * 768 + kt + seg * 16);
        cpa16(sB + off, Bg + (size_t)r * 768 + kt + seg * 16);
    }
}

// ---------------- QKV GEMM (mma.sync + cp.async pipeline) + LN/quant epilogue ----------------
// grid (18, 128), 256 threads, dyn smem 67584
__global__ void __launch_bounds__(256) k_gemm1(
        const float* __restrict__ qkv_alpha,
        const float* __restrict__ nqw, const float* __restrict__ nqb,
        const float* __restrict__ nkw, const float* __restrict__ nkb){
    extern __shared__ int smw[];
    uint32_t smb = smem_u32(smw);
    int tid = threadIdx.x, lane = tid & 31, wid = tid >> 5;
    int wrBase = (wid >> 2) * 64;
    int wcBase = (wid & 3) * 32;
    int rowBase = blockIdx.y << 7, colBase = blockIdx.x << 7;
    const s8* Ag = g_xq + (size_t)rowBase * 768;
    const s8* Bg = g_wq + (size_t)colBase * 768;

    int acc[4][4][4];
#pragma unroll
    for (int mt = 0; mt < 4; mt++)
#pragma unroll
        for (int nt = 0; nt < 4; nt++)
#pragma unroll
            for (int q = 0; q < 4; q++) acc[mt][nt][q] = 0;

    gemm_stage_load(smb, 0, tid, Ag, Bg, 0);
    CPA_COMMIT();
    for (int kc = 0; kc < 6; kc++){
        if (kc < 5){
            gemm_stage_load(smb, (kc + 1) & 1, tid, Ag, Bg, (kc + 1) * 128);
            CPA_COMMIT();
            CPA_WAIT(1);
        } else {
            CPA_WAIT(0);
        }
        __syncthreads();
        const s8* Atile = (const s8*)smw + (kc & 1) * 32768;
        const s8* Btile = Atile + 16384;
        gemm_stage_compute(Atile, Btile, lane, wrBase, wcBase, acc);
        __syncthreads();
    }

    // stage C tile in smem: [128][132]
    int* Cs = smw;
#pragma unroll
    for (int mt = 0; mt < 4; mt++)
#pragma unroll
        for (int nt = 0; nt < 4; nt++){
            int r0 = wrBase + mt * 16 + (lane >> 2);
            int cl = wcBase + nt * 8 + 2 * (lane & 3);
            Cs[r0 * 132 + cl]           = acc[mt][nt][0];
            Cs[r0 * 132 + cl + 1]       = acc[mt][nt][1];
            Cs[(r0 + 8) * 132 + cl]     = acc[mt][nt][2];
            Cs[(r0 + 8) * 132 + cl + 1] = acc[mt][nt][3];
        }
    __syncthreads();

    float a_in = g_sc[0];
    for (int it = wid; it < 256; it += 8){
        int r = it >> 1, g = it & 1;
        int th = (blockIdx.x << 1) + g;
        int t  = th / 12, h = th - 12 * t;
        int row = rowBase + r;
        int b_ = row >> 9, n = row & 511;
        int d0 = lane * 2;
        int jg = th * 64;
        float al0 = qkv_alpha[jg + d0], al1 = qkv_alpha[jg + d0 + 1];
        float c0 = __fadd_rn((float)Cs[r*132 + g*64 + d0],     g_bi[jg + d0]);
        float c1 = __fadd_rn((float)Cs[r*132 + g*64 + d0 + 1], g_bi[jg + d0 + 1]);
        if (t == 2){
            float va = g_sc[3];
            float ap0 = __fdiv_rn(va, __fmul_rn(a_in, al0));
            float ap1 = __fdiv_rn(va, __fmul_rn(a_in, al1));
            float r0 = fminf(fmaxf(__fdiv_rn(c0, ap0), -4.f), 3.f);
            float r1 = fminf(fmaxf(__fdiv_rn(c1, ap1), -4.f), 3.f);
            s8* dst = g_v2t + (size_t)(b_*12 + h) * 64 * 512;
            dst[(size_t)d0 * 512 + n]       = (s8)(int)rintf(r0);
            dst[(size_t)(d0+1) * 512 + n]   = (s8)(int)rintf(r1);
        } else {
            float xs0 = __fmul_rn(c0, al0), xs1 = __fmul_rn(c1, al1);
            float ssum = warp_sum(__fadd_rn(xs0, xs1));
            float mean = __fdiv_rn(ssum, 64.0f);
            float dv0 = __fadd_rn(xs0, -mean), dv1 = __fadd_rn(xs1, -mean);
            float vs = warp_sum(__fadd_rn(__fmul_rn(dv0, dv0), __fmul_rn(dv1, dv1)));
            float stdv = __fsqrt_rn(__fdiv_rn(vs, 63.0f));
            float den = __fadd_rn(stdv, 1e-5f);
            float xh0 = __fdiv_rn(dv0, den), xh1 = __fdiv_rn(dv1, den);
            const float* w  = (t == 0) ? nqw : nkw;
            const float* bb = (t == 0) ? nqb : nkb;
            float act = (t == 0) ? g_sc[1] : g_sc[2];
            float w0 = w[d0], w1 = w[d0 + 1];
            float alp0 = __fdiv_rn(act, w0), alp1 = __fdiv_rn(act, w1);
            float bi0 = __fdiv_rn(bb[d0], w0), bi1 = __fdiv_rn(bb[d0 + 1], w1);
            float r0 = fminf(fmaxf(__fdiv_rn(__fadd_rn(xh0, bi0), alp0), -4.f), 3.f);
            float r1 = fminf(fmaxf(__fdiv_rn(__fadd_rn(xh1, bi1), alp1), -4.f), 3.f);
            s8* dst = (t == 0) ? g_q2 : g_k2;
            size_t o = ((size_t)(b_*12 + h) * 512 + n) * 64 + d0;
            dst[o]     = (s8)(int)rintf(r0);
            dst[o + 1] = (s8)(int)rintf(r1);
        }
    }
}

// ---------------- attention: 2 q-rows per thread, 8 k-slices ----------------
// grid (384, 8), 256 threads, dyn smem 111040 B
// K row ki at int offset ki*16 + (ki>>6)*4 -> 8 slices of 64 rows land on
// distinct bank groups (4s mod 32). Each K/V 64B load feeds 32 dp4a (2 q rows).
#define DP16(sacc, ar, b0, b1, b2, b3)                   \
    sacc = __dp4a((ar)[0],  (b0).x, sacc); sacc = __dp4a((ar)[1],  (b0).y, sacc); \
    sacc = __dp4a((ar)[2],  (b0).z, sacc); sacc = __dp4a((ar)[3],  (b0).w, sacc); \
    sacc = __dp4a((ar)[4],  (b1).x, sacc); sacc = __dp4a((ar)[5],  (b1).y, sacc); \
    sacc = __dp4a((ar)[6],  (b1).z, sacc); sacc = __dp4a((ar)[7],  (b1).w, sacc); \
    sacc = __dp4a((ar)[8],  (b2).x, sacc); sacc = __dp4a((ar)[9],  (b2).y, sacc); \
    sacc = __dp4a((ar)[10], (b2).z, sacc); sacc = __dp4a((ar)[11], (b2).w, sacc); \
    sacc = __dp4a((ar)[12], (b3).x, sacc); sacc = __dp4a((ar)[13], (b3).y, sacc); \
    sacc = __dp4a((ar)[14], (b3).z, sacc); sacc = __dp4a((ar)[15], (b3).w, sacc)

__global__ void k_attn(){
    extern __shared__ int smw[];
    int*   qs   = smw;                        // 1024 ints
    int*   ks   = smw + 1024;                 // 8240 ints (staggered rows)
    int*   vTw  = smw + 9264;                 // 64*132 = 8448 ints
    int*   es   = smw + 17712;                // 64*132 = 8448 ints
    float* rs2  = (float*)(smw + 26160);      // 512 floats [64][8]
    float* rsum = rs2 + 512;                  // 64
    s8*    lut  = (s8*)(rsum + 64);           // 64 x 64

    int tid = threadIdx.x;
    int bh = blockIdx.x, qt = blockIdx.y;
    size_t base = (size_t)bh * 512 * 64;

    const int4* qg = (const int4*)(g_q2 + base + (size_t)qt * 64 * 64);
    ((int4*)qs)[tid] = qg[tid];
    const int4* kg = (const int4*)(g_k2 + base);
#pragma unroll
    for (int i = tid; i < 2048; i += 256){
        int ki = i >> 2, seg = i & 3;
        *(int4*)&ks[ki * 16 + (ki >> 6) * 4 + seg * 4] = kg[i];
    }
    const int4* vg = (const int4*)(g_v2t + base);
#pragma unroll
    for (int i = tid; i < 2048; i += 256){
        int d = i >> 5, seg = i & 31;
        ((int4*)&vTw[d * 132])[seg] = vg[i];
    }
    __syncthreads();

    int qi2 = tid >> 3, qr = tid & 7;     // q rows {qi2, qi2+32}, k slice [qr*64, qr*64+64)
    int areg0[16], areg1[16];
#pragma unroll
    for (int w = 0; w < 16; w++){
        areg0[w] = qs[qi2 * 16 + w];
        areg1[w] = qs[(qi2 + 32) * 16 + w];
    }

    float cs1 = g_sc[6];
    float psum0 = 0.f, psum1 = 0.f;
    int packed0 = 0, packed1 = 0;
    const int* ksq = ks + qr * 1028;      // qr*64 rows * 16 ints + qr*4 stagger
    for (int i = 0; i < 64; i++){
        const int4* kr = (const int4*)(ksq + i * 16);
        int4 b0 = kr[0], b1 = kr[1], b2 = kr[2], b3 = kr[3];
        int s0 = 0, s1 = 0;
        DP16(s0, areg0, b0, b1, b2, b3);
        DP16(s1, areg1, b0, b1, b2, b3);
        float e0 = truncf(__fmul_rn(__fmul_rn(cs1, (float)s0), 128.0f));
        float e1 = truncf(__fmul_rn(__fmul_rn(cs1, (float)s1), 128.0f));
        int ei0 = (int)rintf(__fmul_rn(e0, 0.0078125f));
        int ei1 = (int)rintf(__fmul_rn(e1, 0.0078125f));
        psum0 = __fadd_rn(psum0, p2i(ei0));
        psum1 = __fadd_rn(psum1, p2i(ei1));
        packed0 |= (ei0 & 0xff) << ((i & 3) * 8);
        packed1 |= (ei1 & 0xff) << ((i & 3) * 8);
        if ((i & 3) == 3){
            int k4 = qr * 16 + (i >> 2);
            es[qi2 * 132 + k4]        = packed0;
            es[(qi2 + 32) * 132 + k4] = packed1;
            packed0 = 0; packed1 = 0;
        }
    }
    rs2[qi2 * 8 + qr]        = psum0;
    rs2[(qi2 + 32) * 8 + qr] = psum1;
    __syncthreads();
    if (tid < 64){
        const float* r8 = rs2 + tid * 8;
        float s = r8[0];
#pragma unroll
        for (int j = 1; j < 8; j++) s = __fadd_rn(s, r8[j]);
        rsum[tid] = s;
    }
    __syncthreads();

    float aa = g_sc[4];
    for (int w = tid; w < 4096; w += 256){
        int row = w >> 6, j = w & 63;
        float p = p2i(j - 32);
        float su = rsum[row];
        float r = fminf(fmaxf(__fdiv_rn(__fdiv_rn(p, su), aa), 0.f), 7.f);
        lut[w] = (s8)(int)rintf(r);
    }
    __syncthreads();

    for (int w = tid; w < 8192; w += 256){
        int q2i = w >> 7, k4 = w & 127;
        int e4 = es[q2i * 132 + k4];
        const s8* lr = lut + (q2i << 6);
        int out = 0;
#pragma unroll
        for (int b = 0; b < 4; b++){
            int ei = (int)(s8)(e4 >> (b * 8));
            int j = min(max(ei + 32, 0), 63);
            out |= ((int)lr[j]) << (b * 8);
        }
        es[q2i * 132 + k4] = out;
    }
    __syncthreads();

    // AV: thread owns q rows {qi2, qi2+32}, d = qr + 8*dd (dd < 8)
    int acc0[8], acc1[8];
#pragma unroll
    for (int dd = 0; dd < 8; dd++){ acc0[dd] = 0; acc1[dd] = 0; }
#pragma unroll
    for (int c = 0; c < 8; c++){
        int aw0[16], aw1[16];
#pragma unroll
        for (int w = 0; w < 16; w++){
            aw0[w] = es[qi2 * 132 + c * 16 + w];
            aw1[w] = es[(qi2 + 32) * 132 + c * 16 + w];
        }
#pragma unroll
        for (int dd = 0; dd < 8; dd++){
            int d = qr + 8 * dd;
            const int4* vr = (const int4*)&vTw[d * 132 + c * 16];
            int4 v0 = vr[0], v1 = vr[1], v2 = vr[2], v3 = vr[3];
            int s0 = acc0[dd], s1 = acc1[dd];
            DP16(s0, aw0, v0, v1, v2, v3);
            DP16(s1, aw1, v0, v1, v2, v3);
            acc0[dd] = s0; acc1[dd] = s1;
        }
    }
    float apx = g_sc[7];
    int b_ = bh / 12, h = bh - 12 * b_;
    int row0 = b_ * 512 + qt * 64 + qi2;
    s8* dst0 = g_x1 + (size_t)row0 * 768 + h * 64;
    s8* dst1 = g_x1 + (size_t)(row0 + 32) * 768 + h * 64;
#pragma unroll
    for (int dd = 0; dd < 8; dd++){
        float r0 = fminf(fmaxf(__fdiv_rn((float)acc0[dd], apx), -4.f), 3.f);
        float r1 = fminf(fmaxf(__fdiv_rn((float)acc1[dd], apx), -4.f), 3.f);
        dst0[qr + 8 * dd] = (s8)(int)rintf(r0);
        dst1[qr + 8 * dd] = (s8)(int)rintf(r1);
    }
}

// ---------------- projection GEMM (mma.sync + cp.async pipeline) ----------------
// grid (6, 128), 256 threads, dyn smem 65536
__global__ void __launch_bounds__(256) k_gemm2(
        const float* __restrict__ palpha, const float* __restrict__ pbias,
        float* __restrict__ out){
    extern __shared__ int smw[];
    uint32_t smb = smem_u32(smw);
    int tid = threadIdx.x, lane = tid & 31, wid = tid >> 5;
    int wrBase = (wid >> 2) * 64;
    int wcBase = (wid & 3) * 32;
    int rowBase = blockIdx.y << 7, colBase = blockIdx.x << 7;
    const s8* Ag = g_x1 + (size_t)rowBase * 768;
    const s8* Bg = g_pw + (size_t)colBase * 768;

    int acc[4][4][4];
#pragma unroll
    for (int mt = 0; mt < 4; mt++)
#pragma unroll
        for (int nt = 0; nt < 4; nt++)
#pragma unroll
            for (int q = 0; q < 4; q++) acc[mt][nt][q] = 0;

    gemm_stage_load(smb, 0, tid, Ag, Bg, 0);
    CPA_COMMIT();
    for (int kc = 0; kc < 6; kc++){
        if (kc < 5){
            gemm_stage_load(smb, (kc + 1) & 1, tid, Ag, Bg, (kc + 1) * 128);
            CPA_COMMIT();
            CPA_WAIT(1);
        } else {
            CPA_WAIT(0);
        }
        __syncthreads();
        const s8* Atile = (const s8*)smw + (kc & 1) * 32768;
        const s8* Btile = Atile + 16384;
        gemm_stage_compute(Atile, Btile, lane, wrBase, wcBase, acc);
        __syncthreads();
    }

    float pa = g_sc[5];
#pragma unroll
    for (int mt = 0; mt < 4; mt++)
#pragma unroll
        for (int nt = 0; nt < 4; nt++){
            int r0 = rowBase + wrBase + mt * 16 + (lane >> 2);
            int c  = colBase + wcBase + nt * 8 + 2 * (lane & 3);
            float al0 = palpha[c], al1 = palpha[c + 1];
            float bi0 = pbias[c],  bi1 = pbias[c + 1];
            out[(size_t)r0 * 768 + c]
                = __fadd_rn(__fmul_rn(__fmul_rn((float)acc[mt][nt][0], al0), pa), bi0);
            out[(size_t)r0 * 768 + c + 1]
                = __fadd_rn(__fmul_rn(__fmul_rn((float)acc[mt][nt][1], al1), pa), bi1);
            out[(size_t)(r0 + 8) * 768 + c]
                = __fadd_rn(__fmul_rn(__fmul_rn((float)acc[mt][nt][2], al0), pa), bi0);
            out[(size_t)(r0 + 8) * 768 + c + 1]
                = __fadd_rn(__fmul_rn(__fmul_rn((float)acc[mt][nt][3], al1), pa), bi1);
        }
}

// ---------------- launch ----------------
extern "C" void kernel_launch(void* const* d_in, const int* in_sizes, int n_in,
                              void* d_out, int out_size){
    const float* x0          = (const float*)d_in[0];
    const float* qkv_w       = (const float*)d_in[1];
    const float* qkv_alpha   = (const float*)d_in[2];
    const float* qkv_bias    = (const float*)d_in[3];
    const float* qkv_act_al  = (const float*)d_in[4];
    const float* proj_w      = (const float*)d_in[5];
    const float* proj_alpha  = (const float*)d_in[6];
    const float* proj_bias   = (const float*)d_in[7];
    const float* proj_act_al = (const float*)d_in[8];
    const float* normq_w     = (const float*)d_in[9];
    const float* normq_b     = (const float*)d_in[10];
    const float* normk_w     = (const float*)d_in[11];
    const float* normk_b     = (const float*)d_in[12];
    const float* qact        = (const float*)d_in[13];
    const float* kact        = (const float*)d_in[14];
    const float* vact        = (const float*)d_in[15];
    const float* attnact     = (const float*)d_in[16];
    float* out = (float*)d_out;

    cudaFuncSetAttribute(k_gemm1, cudaFuncAttributeMaxDynamicSharedMemorySize, 67584);
    cudaFuncSetAttribute(k_gemm2, cudaFuncAttributeMaxDynamicSharedMemorySize, 65536);
    cudaFuncSetAttribute(k_attn,  cudaFuncAttributeMaxDynamicSharedMemorySize, 111040);

    k_scalars<<<1, 256>>>(qkv_act_al, qact, kact, vact, attnact, proj_act_al,
                          qkv_bias, qkv_alpha);
    k_quant_xw<<<4800, 256>>>(x0, qkv_w, qkv_alpha);
    k_gemm1<<<dim3(18, 128), 256, 67584>>>(qkv_alpha, normq_w, normq_b, normk_w, normk_b);
    k_attn<<<dim3(384, 8), 256, 111040>>>();
    k_quant_pw<<<576, 256>>>(proj_w, proj_alpha);
    k_gemm2<<<dim3(6, 128), 256, 65536>>>(proj_alpha, proj_bias, out);
}

// round 12
// speedup vs baseline: 1.7247x; 1.0180x over previous
#include <cuda_runtime.h>
#include <cstdint>
#include <cstddef>

#define BB 32
#define NN 512
#define CC 768
#define HH 12
#define HD 64
#define MTOT (BB*NN)      // 16384
#define NC3 (3*CC)        // 2304

typedef signed char s8;

// ---------------- device scratch (allocation-free) ----------------
__device__ float g_sc[8]; // 0:a_in 1:qa 2:ka 3:va 4:aa 5:pa 6:cs1 7:apx
__device__ s8    g_xq[MTOT*CC];
__device__ s8    g_wq[NC3*CC];
__device__ float g_bi[NC3];
__device__ s8    g_q2[BB*HH*NN*HD];
__device__ s8    g_k2[BB*HH*NN*HD];
__device__ s8    g_v2t[BB*HH*HD*NN];   // [bh][d][n]
__device__ s8    g_x1[MTOT*CC];
__device__ s8    g_pw[CC*CC];

__device__ __forceinline__ float warp_sum(float v){
#pragma unroll
    for (int o = 16; o > 0; o >>= 1)
        v = __fadd_rn(v, __shfl_xor_sync(0xffffffffu, v, o));
    return v;
}

__device__ __forceinline__ s8 q_rc(float v, float a, float lo, float hi){
    float r = __fdiv_rn(v, a);
    r = fminf(fmaxf(r, lo), hi);
    return (s8)(int)rintf(r);
}

// exact 2^ei for integer ei >= -126
__device__ __forceinline__ float p2i(int ei){
    int ec = max(ei, -126);
    return __int_as_float((ec + 127) << 23);
}

__device__ __forceinline__ void mma_s8(int* d, const int* a, const int* b){
    asm volatile(
        "mma.sync.aligned.m16n8k32.row.col.s32.s8.s8.s32 "
        "{%0,%1,%2,%3}, {%4,%5,%6,%7}, {%8,%9}, {%0,%1,%2,%3};"
        : "+r"(d[0]), "+r"(d[1]), "+r"(d[2]), "+r"(d[3])
        : "r"(a[0]), "r"(a[1]), "r"(a[2]), "r"(a[3]), "r"(b[0]), "r"(b[1]));
}

__device__ __forceinline__ uint32_t smem_u32(const void* p){
    uint32_t a;
    asm("{ .reg .u64 t; cvta.to.shared.u64 t, %1; cvt.u32.u64 %0, t; }" : "=r"(a) : "l"(p));
    return a;
}
__device__ __forceinline__ void cpa16(uint32_t dst, const void* src){
    asm volatile("cp.async.ca.shared.global [%0], [%1], 16;" :: "r"(dst), "l"(src));
}
#define CPA_COMMIT() asm volatile("cp.async.commit_group;" ::: "memory")
#define CPA_WAIT(n)  asm volatile("cp.async.wait_group %0;" :: "n"(n) : "memory")

// ---------------- scalar means + integer bias ----------------
__global__ void k_scalars(const float* __restrict__ qaa, const float* __restrict__ qact,
                          const float* __restrict__ kact, const float* __restrict__ vact,
                          const float* __restrict__ aact, const float* __restrict__ paa,
                          const float* __restrict__ qkv_bias, const float* __restrict__ qkv_alpha){
    int tid = threadIdx.x;
    if (tid < 32){
        int lane = tid;
        float s = 0.f;
        for (int i = lane; i < 768; i += 32) s = __fadd_rn(s, qaa[i]);
        float a_in = __fdiv_rn(warp_sum(s), 768.0f);
        s = 0.f;
        for (int i = lane; i < 768; i += 32) s = __fadd_rn(s, paa[i]);
        float pa = __fdiv_rn(warp_sum(s), 768.0f);
        float t;
        t = (lane < 12) ? qact[lane] : 0.f; float qa = __fdiv_rn(warp_sum(t), 12.0f);
        t = (lane < 12) ? kact[lane] : 0.f; float ka = __fdiv_rn(warp_sum(t), 12.0f);
        t = (lane < 12) ? vact[lane] : 0.f; float va = __fdiv_rn(warp_sum(t), 12.0f);
        t = (lane < 12) ? aact[lane] : 0.f; float aa = __fdiv_rn(warp_sum(t), 12.0f);
        if (lane == 0){
            g_sc[0] = a_in; g_sc[1] = qa; g_sc[2] = ka; g_sc[3] = va; g_sc[4] = aa; g_sc[5] = pa;
            float sm = __fmul_rn(__fmul_rn(0.125f, qa), ka);
            g_sc[6] = __fmul_rn(1.4426950408889634f, sm);
            g_sc[7] = __fdiv_rn(pa, __fmul_rn(aa, va));
        }
    }
    __syncthreads();
    float a_in = g_sc[0];
    for (int j = tid; j < NC3; j += 256)
        g_bi[j] = truncf(__fdiv_rn(__fdiv_rn(qkv_bias[j], a_in), qkv_alpha[j]));
}

// ---------------- fused input+weight quantization ----------------
__global__ void k_quant_xw(const float* __restrict__ x, const float* __restrict__ w,
                           const float* __restrict__ al){
    if (blockIdx.x < 3072){
        float a = g_sc[0];
        int base = blockIdx.x * 1024 + threadIdx.x;
#pragma unroll
        for (int p = 0; p < 4; p++){
            int idx = base + p * 256;
            float4 v = ((const float4*)x)[idx];
            char4 c;
            c.x = q_rc(v.x, a, -8.f, 7.f); c.y = q_rc(v.y, a, -8.f, 7.f);
            c.z = q_rc(v.z, a, -8.f, 7.f); c.w = q_rc(v.w, a, -8.f, 7.f);
            ((char4*)g_xq)[idx] = c;
        }
    } else {
        int idx = (blockIdx.x - 3072) * 256 + threadIdx.x;
        int row = idx / 192;
        float a = al[row];
        float4 v = ((const float4*)w)[idx];
        char4 c;
        c.x = q_rc(v.x, a, -8.f, 7.f); c.y = q_rc(v.y, a, -8.f, 7.f);
        c.z = q_rc(v.z, a, -8.f, 7.f); c.w = q_rc(v.w, a, -8.f, 7.f);
        ((char4*)g_wq)[idx] = c;
    }
}

__global__ void k_quant_pw(const float* __restrict__ w, const float* __restrict__ al){
    int idx = blockIdx.x * 256 + threadIdx.x;
    int row = idx / 192;
    float a = al[row];
    float4 v = ((const float4*)w)[idx];
    char4 c;
    c.x = q_rc(v.x, a, -8.f, 7.f); c.y = q_rc(v.y, a, -8.f, 7.f);
    c.z = q_rc(v.z, a, -8.f, 7.f); c.w = q_rc(v.w, a, -8.f, 7.f);
    ((char4*)g_pw)[idx] = c;
}

// ---------------- GEMM compute tile (shared by gemm1/gemm2) ----------------
__device__ __forceinline__ void gemm_stage_compute(
        const s8* Atile, const s8* Btile, int lane, int wrBase, int wcBase,
        int acc[4][4][4]){
#pragma unroll
    for (int s = 0; s < 4; s++){
        int c4 = (lane & 3) * 4;
        int afr[4][4];
#pragma unroll
        for (int mt = 0; mt < 4; mt++){
            int r0 = wrBase + mt * 16 + (lane >> 2);
            int r1 = r0 + 8;
            afr[mt][0] = *(const int*)(Atile + r0*128 + (((2*s  ) ^ (r0 & 7)) * 16) + c4);
            afr[mt][1] = *(const int*)(Atile + r1*128 + (((2*s  ) ^ (r1 & 7)) * 16) + c4);
            afr[mt][2] = *(const int*)(Atile + r0*128 + (((2*s+1) ^ (r0 & 7)) * 16) + c4);
            afr[mt][3] = *(const int*)(Atile + r1*128 + (((2*s+1) ^ (r1 & 7)) * 16) + c4);
        }
        int bfr[4][2];
#pragma unroll
        for (int nt = 0; nt < 4; nt++){
            int c0 = wcBase + nt * 8 + (lane >> 2);
            bfr[nt][0] = *(const int*)(Btile + c0*128 + (((2*s  ) ^ (c0 & 7)) * 16) + c4);
            bfr[nt][1] = *(const int*)(Btile + c0*128 + (((2*s+1) ^ (c0 & 7)) * 16) + c4);
        }
#pragma unroll
        for (int mt = 0; mt < 4; mt++)
#pragma unroll
            for (int nt = 0; nt < 4; nt++)
                mma_s8(acc[mt][nt], afr[mt], bfr[nt]);
    }
}

__device__ __forceinline__ void gemm_stage_load(
        uint32_t smb, int stage, int tid,
        const s8* __restrict__ Ag, const s8* __restrict__ Bg, int kt){
    uint32_t sA = smb + stage * 32768;
    uint32_t sB = sA + 16384;
#pragma unroll
    for (int p = 0; p < 4; p++){
        int idx = tid + p * 256;
        int r = idx >> 3, seg = idx & 7;
        uint32_t off = r * 128 + ((seg ^ (r & 7)) * 16);
        cpa16(sA + off, Ag + (size_t)r * 768 + kt + seg * 16);
        cpa16(sB + off, Bg + (size_t)r * 768 + kt + seg * 16);
    }
}

// ---------------- QKV GEMM (mma.sync + cp.async pipeline) + LN/quant epilogue ----------------
// grid (18, 128), 256 threads, dyn smem 67584
__global__ void __launch_bounds__(256) k_gemm1(
        const float* __restrict__ qkv_alpha,
        const float* __restrict__ nqw, const float* __restrict__ nqb,
        const float* __restrict__ nkw, const float* __restrict__ nkb){
    extern __shared__ int smw[];
    uint32_t smb = smem_u32(smw);
    int tid = threadIdx.x, lane = tid & 31, wid = tid >> 5;
    int wrBase = (wid >> 2) * 64;
    int wcBase = (wid & 3) * 32;
    int rowBase = blockIdx.y << 7, colBase = blockIdx.x << 7;
    const s8* Ag = g_xq + (size_t)rowBase * 768;
    const s8* Bg = g_wq + (size_t)colBase * 768;

    int acc[4][4][4];
#pragma unroll
    for (int mt = 0; mt < 4; mt++)
#pragma unroll
        for (int nt = 0; nt < 4; nt++)
#pragma unroll
            for (int q = 0; q < 4; q++) acc[mt][nt][q] = 0;

    gemm_stage_load(smb, 0, tid, Ag, Bg, 0);
    CPA_COMMIT();
    for (int kc = 0; kc < 6; kc++){
        if (kc < 5){
            gemm_stage_load(smb, (kc + 1) & 1, tid, Ag, Bg, (kc + 1) * 128);
            CPA_COMMIT();
            CPA_WAIT(1);
        } else {
            CPA_WAIT(0);
        }
        __syncthreads();
        const s8* Atile = (const s8*)smw + (kc & 1) * 32768;
        const s8* Btile = Atile + 16384;
        gemm_stage_compute(Atile, Btile, lane, wrBase, wcBase, acc);
        __syncthreads();
    }

    // stage C tile in smem: [128][132]
    int* Cs = smw;
#pragma unroll
    for (int mt = 0; mt < 4; mt++)
#pragma unroll
        for (int nt = 0; nt < 4; nt++){
            int r0 = wrBase + mt * 16 + (lane >> 2);
            int cl = wcBase + nt * 8 + 2 * (lane & 3);
            Cs[r0 * 132 + cl]           = acc[mt][nt][0];
            Cs[r0 * 132 + cl + 1]       = acc[mt][nt][1];
            Cs[(r0 + 8) * 132 + cl]     = acc[mt][nt][2];
            Cs[(r0 + 8) * 132 + cl + 1] = acc[mt][nt][3];
        }
    __syncthreads();

    float a_in = g_sc[0];
    for (int it = wid; it < 256; it += 8){
        int r = it >> 1, g = it & 1;
        int th = (blockIdx.x << 1) + g;
        int t  = th / 12, h = th - 12 * t;
        int row = rowBase + r;
        int b_ = row >> 9, n = row & 511;
        int d0 = lane * 2;
        int jg = th * 64;
        float al0 = qkv_alpha[jg + d0], al1 = qkv_alpha[jg + d0 + 1];
        float c0 = __fadd_rn((float)Cs[r*132 + g*64 + d0],     g_bi[jg + d0]);
        float c1 = __fadd_rn((float)Cs[r*132 + g*64 + d0 + 1], g_bi[jg + d0 + 1]);
        if (t == 2){
            float va = g_sc[3];
            float ap0 = __fdiv_rn(va, __fmul_rn(a_in, al0));
            float ap1 = __fdiv_rn(va, __fmul_rn(a_in, al1));
            float r0 = fminf(fmaxf(__fdiv_rn(c0, ap0), -4.f), 3.f);
            float r1 = fminf(fmaxf(__fdiv_rn(c1, ap1), -4.f), 3.f);
            s8* dst = g_v2t + (size_t)(b_*12 + h) * 64 * 512;
            dst[(size_t)d0 * 512 + n]       = (s8)(int)rintf(r0);
            dst[(size_t)(d0+1) * 512 + n]   = (s8)(int)rintf(r1);
        } else {
            float xs0 = __fmul_rn(c0, al0), xs1 = __fmul_rn(c1, al1);
            float ssum = warp_sum(__fadd_rn(xs0, xs1));
            float mean = __fdiv_rn(ssum, 64.0f);
            float dv0 = __fadd_rn(xs0, -mean), dv1 = __fadd_rn(xs1, -mean);
            float vs = warp_sum(__fadd_rn(__fmul_rn(dv0, dv0), __fmul_rn(dv1, dv1)));
            float stdv = __fsqrt_rn(__fdiv_rn(vs, 63.0f));
            float den = __fadd_rn(stdv, 1e-5f);
            float xh0 = __fdiv_rn(dv0, den), xh1 = __fdiv_rn(dv1, den);
            const float* w  = (t == 0) ? nqw : nkw;
            const float* bb = (t == 0) ? nqb : nkb;
            float act = (t == 0) ? g_sc[1] : g_sc[2];
            float w0 = w[d0], w1 = w[d0 + 1];
            float alp0 = __fdiv_rn(act, w0), alp1 = __fdiv_rn(act, w1);
            float bi0 = __fdiv_rn(bb[d0], w0), bi1 = __fdiv_rn(bb[d0 + 1], w1);
            float r0 = fminf(fmaxf(__fdiv_rn(__fadd_rn(xh0, bi0), alp0), -4.f), 3.f);
            float r1 = fminf(fmaxf(__fdiv_rn(__fadd_rn(xh1, bi1), alp1), -4.f), 3.f);
            s8* dst = (t == 0) ? g_q2 : g_k2;
            size_t o = ((size_t)(b_*12 + h) * 512 + n) * 64 + d0;
            dst[o]     = (s8)(int)rintf(r0);
            dst[o + 1] = (s8)(int)rintf(r1);
        }
    }
}

// ---------------- attention: 4 q-rows per thread, 16 k-slices ----------------
// grid (384, 8), 256 threads, dyn smem 113152 B (qs 4096 + ks 33024 + vTw 33792
//  + es 33792 + rs2 4096 + rsum 256 + lut 4096)
#define DP16(sacc, ar, b0, b1, b2, b3)                   \
    sacc = __dp4a((ar)[0],  (b0).x, sacc); sacc = __dp4a((ar)[1],  (b0).y, sacc); \
    sacc = __dp4a((ar)[2],  (b0).z, sacc); sacc = __dp4a((ar)[3],  (b0).w, sacc); \
    sacc = __dp4a((ar)[4],  (b1).x, sacc); sacc = __dp4a((ar)[5],  (b1).y, sacc); \
    sacc = __dp4a((ar)[6],  (b1).z, sacc); sacc = __dp4a((ar)[7],  (b1).w, sacc); \
    sacc = __dp4a((ar)[8],  (b2).x, sacc); sacc = __dp4a((ar)[9],  (b2).y, sacc); \
    sacc = __dp4a((ar)[10], (b2).z, sacc); sacc = __dp4a((ar)[11], (b2).w, sacc); \
    sacc = __dp4a((ar)[12], (b3).x, sacc); sacc = __dp4a((ar)[13], (b3).y, sacc); \
    sacc = __dp4a((ar)[14], (b3).z, sacc); sacc = __dp4a((ar)[15], (b3).w, sacc)

__global__ void __launch_bounds__(256, 2) k_attn(){
    extern __shared__ int smw[];
    int*   qs   = smw;                        // 1024
    int*   ks   = smw + 1024;                 // 8256 (staggered per 32 rows)
    int*   vTw  = smw + 9280;                 // 8448
    int*   es   = smw + 17728;                // 8448
    float* rs2  = (float*)(smw + 26176);      // 1024 floats [64][16]
    float* rsum = rs2 + 1024;                 // 64
    s8*    lut  = (s8*)(rsum + 64);           // 64 x 64 = 4096 B

    int tid = threadIdx.x;
    int bh = blockIdx.x, qt = blockIdx.y;
    size_t base = (size_t)bh * 512 * 64;

    const int4* qg = (const int4*)(g_q2 + base + (size_t)qt * 4096);
    ((int4*)qs)[tid] = qg[tid];
    const int4* kg = (const int4*)(g_k2 + base);
#pragma unroll
    for (int i = tid; i < 2048; i += 256){
        int ki = i >> 2, seg = i & 3;
        *(int4*)&ks[ki * 16 + (ki >> 5) * 4 + seg * 4] = kg[i];
    }
    const int4* vg = (const int4*)(g_v2t + base);
#pragma unroll
    for (int i = tid; i < 2048; i += 256){
        int d = i >> 5, seg = i & 31;
        ((int4*)&vTw[d * 132])[seg] = vg[i];
    }
    __syncthreads();

    int qq = tid >> 4, qr = tid & 15;     // q rows {qq+16j}, k slice [qr*32, +32)
    int areg[4][16];
#pragma unroll
    for (int j = 0; j < 4; j++)
#pragma unroll
        for (int w = 0; w < 16; w++) areg[j][w] = qs[(qq + 16*j) * 16 + w];

    float cs1 = g_sc[6];
    float psum[4] = {0.f, 0.f, 0.f, 0.f};
    int packed[4] = {0, 0, 0, 0};
    const int* ksq = ks + qr * 516;       // qr*32 rows * 16 ints + qr*4 stagger
    for (int i = 0; i < 32; i++){
        const int4* kr = (const int4*)(ksq + i * 16);
        int4 b0 = kr[0], b1 = kr[1], b2 = kr[2], b3 = kr[3];
#pragma unroll
        for (int j = 0; j < 4; j++){
            int s = 0;
            DP16(s, areg[j], b0, b1, b2, b3);
            float e = truncf(__fmul_rn(__fmul_rn(cs1, (float)s), 128.0f));
            int ei = (int)rintf(__fmul_rn(e, 0.0078125f));
            psum[j] = __fadd_rn(psum[j], p2i(ei));
            packed[j] |= (ei & 0xff) << ((i & 3) * 8);
        }
        if ((i & 3) == 3){
            int k4 = qr * 8 + (i >> 2);
#pragma unroll
            for (int j = 0; j < 4; j++){
                es[(qq + 16*j) * 132 + k4] = packed[j];
                packed[j] = 0;
            }
        }
    }
#pragma unroll
    for (int j = 0; j < 4; j++)
        rs2[(qq + 16*j) * 16 + qr] = psum[j];
    __syncthreads();
    if (tid < 64){
        const float* r16 = rs2 + tid * 16;
        float s = r16[0];
#pragma unroll
        for (int j = 1; j < 16; j++) s = __fadd_rn(s, r16[j]);
        rsum[tid] = s;
    }
    __syncthreads();

    float aa = g_sc[4];
    for (int w = tid; w < 4096; w += 256){
        int row = w >> 6, j = w & 63;
        float p = p2i(j - 32);
        float su = rsum[row];
        float r = fminf(fmaxf(__fdiv_rn(__fdiv_rn(p, su), aa), 0.f), 7.f);
        lut[w] = (s8)(int)rintf(r);
    }
    __syncthreads();

    for (int w = tid; w < 8192; w += 256){
        int q2i = w >> 7, k4 = w & 127;
        int e4 = es[q2i * 132 + k4];
        const s8* lr = lut + (q2i << 6);
        int out = 0;
#pragma unroll
        for (int b = 0; b < 4; b++){
            int ei = (int)(s8)(e4 >> (b * 8));
            int j = min(max(ei + 32, 0), 63);
            out |= ((int)lr[j]) << (b * 8);
        }
        es[q2i * 132 + k4] = out;
    }
    __syncthreads();

    // AV: q rows {qq+16j}, d = qr + 16*dd (dd < 4)
    int acc[4][4];
#pragma unroll
    for (int j = 0; j < 4; j++)
#pragma unroll
        for (int dd = 0; dd < 4; dd++) acc[j][dd] = 0;
#pragma unroll
    for (int c = 0; c < 8; c++){
        int aw[4][16];
#pragma unroll
        for (int j = 0; j < 4; j++)
#pragma unroll
            for (int w = 0; w < 16; w++)
                aw[j][w] = es[(qq + 16*j) * 132 + c * 16 + w];
#pragma unroll
        for (int dd = 0; dd < 4; dd++){
            int d = qr + 16 * dd;
            const int4* vr = (const int4*)&vTw[d * 132 + c * 16];
            int4 v0 = vr[0], v1 = vr[1], v2 = vr[2], v3 = vr[3];
#pragma unroll
            for (int j = 0; j < 4; j++){
                int s = acc[j][dd];
                DP16(s, aw[j], v0, v1, v2, v3);
                acc[j][dd] = s;
            }
        }
    }
    float apx = g_sc[7];
    int b_ = bh / 12, h = bh - 12 * b_;
    int row0 = b_ * 512 + qt * 64 + qq;
#pragma unroll
    for (int j = 0; j < 4; j++){
        s8* dst = g_x1 + (size_t)(row0 + 16*j) * 768 + h * 64;
#pragma unroll
        for (int dd = 0; dd < 4; dd++){
            float r = fminf(fmaxf(__fdiv_rn((float)acc[j][dd], apx), -4.f), 3.f);
            dst[qr + 16 * dd] = (s8)(int)rintf(r);
        }
    }
}

// ---------------- projection GEMM (mma.sync + cp.async pipeline) ----------------
// grid (6, 128), 256 threads, dyn smem 65536
__global__ void __launch_bounds__(256) k_gemm2(
        const float* __restrict__ palpha, const float* __restrict__ pbias,
        float* __restrict__ out){
    extern __shared__ int smw[];
    uint32_t smb = smem_u32(smw);
    int tid = threadIdx.x, lane = tid & 31, wid = tid >> 5;
    int wrBase = (wid >> 2) * 64;
    int wcBase = (wid & 3) * 32;
    int rowBase = blockIdx.y << 7, colBase = blockIdx.x << 7;
    const s8* Ag = g_x1 + (size_t)rowBase * 768;
    const s8* Bg = g_pw + (size_t)colBase * 768;

    int acc[4][4][4];
#pragma unroll
    for (int mt = 0; mt < 4; mt++)
#pragma unroll
        for (int nt = 0; nt < 4; nt++)
#pragma unroll
            for (int q = 0; q < 4; q++) acc[mt][nt][q] = 0;

    gemm_stage_load(smb, 0, tid, Ag, Bg, 0);
    CPA_COMMIT();
    for (int kc = 0; kc < 6; kc++){
        if (kc < 5){
            gemm_stage_load(smb, (kc + 1) & 1, tid, Ag, Bg, (kc + 1) * 128);
            CPA_COMMIT();
            CPA_WAIT(1);
        } else {
            CPA_WAIT(0);
        }
        __syncthreads();
        const s8* Atile = (const s8*)smw + (kc & 1) * 32768;
        const s8* Btile = Atile + 16384;
        gemm_stage_compute(Atile, Btile, lane, wrBase, wcBase, acc);
        __syncthreads();
    }

    float pa = g_sc[5];
#pragma unroll
    for (int mt = 0; mt < 4; mt++)
#pragma unroll
        for (int nt = 0; nt < 4; nt++){
            int r0 = rowBase + wrBase + mt * 16 + (lane >> 2);
            int c  = colBase + wcBase + nt * 8 + 2 * (lane & 3);
            float al0 = palpha[c], al1 = palpha[c + 1];
            float bi0 = pbias[c],  bi1 = pbias[c + 1];
            out[(size_t)r0 * 768 + c]
                = __fadd_rn(__fmul_rn(__fmul_rn((float)acc[mt][nt][0], al0), pa), bi0);
            out[(size_t)r0 * 768 + c + 1]
                = __fadd_rn(__fmul_rn(__fmul_rn((float)acc[mt][nt][1], al1), pa), bi1);
            out[(size_t)(r0 + 8) * 768 + c]
                = __fadd_rn(__fmul_rn(__fmul_rn((float)acc[mt][nt][2], al0), pa), bi0);
            out[(size_t)(r0 + 8) * 768 + c + 1]
                = __fadd_rn(__fmul_rn(__fmul_rn((float)acc[mt][nt][3], al1), pa), bi1);
        }
}

// ---------------- launch ----------------
extern "C" void kernel_launch(void* const* d_in, const int* in_sizes, int n_in,
                              void* d_out, int out_size){
    const float* x0          = (const float*)d_in[0];
    const float* qkv_w       = (const float*)d_in[1];
    const float* qkv_alpha   = (const float*)d_in[2];
    const float* qkv_bias    = (const float*)d_in[3];
    const float* qkv_act_al  = (const float*)d_in[4];
    const float* proj_w      = (const float*)d_in[5];
    const float* proj_alpha  = (const float*)d_in[6];
    const float* proj_bias   = (const float*)d_in[7];
    const float* proj_act_al = (const float*)d_in[8];
    const float* normq_w     = (const float*)d_in[9];
    const float* normq_b     = (const float*)d_in[10];
    const float* normk_w     = (const float*)d_in[11];
    const float* normk_b     = (const float*)d_in[12];
    const float* qact        = (const float*)d_in[13];
    const float* kact        = (const float*)d_in[14];
    const float* vact        = (const float*)d_in[15];
    const float* attnact     = (const float*)d_in[16];
    float* out = (float*)d_out;

    cudaFuncSetAttribute(k_gemm1, cudaFuncAttributeMaxDynamicSharedMemorySize, 67584);
    cudaFuncSetAttribute(k_gemm2, cudaFuncAttributeMaxDynamicSharedMemorySize, 65536);
    cudaFuncSetAttribute(k_attn,  cudaFuncAttributeMaxDynamicSharedMemorySize, 113152);

    k_scalars<<<1, 256>>>(qkv_act_al, qact, kact, vact, attnact, proj_act_al,
                          qkv_bias, qkv_alpha);
    k_quant_xw<<<4800, 256>>>(x0, qkv_w, qkv_alpha);
    k_gemm1<<<dim3(18, 128), 256, 67584>>>(qkv_alpha, normq_w, normq_b, normk_w, normk_b);
    k_attn<<<dim3(384, 8), 256, 113152>>>();
    k_quant_pw<<<576, 256>>>(proj_w, proj_alpha);
    k_gemm2<<<dim3(6, 128), 256, 65536>>>(proj_alpha, proj_bias, out);
}